// round 4
// baseline (speedup 1.0000x reference)
#include <cuda_runtime.h>
#include <math.h>
#include <stdint.h>

#define TT 32
#define NN 1024
#define FF 64
#define HH 128
#define H4 512

// ---- scratch (static __device__ arrays; no runtime allocation) ----
__device__ float g_xs[TT * NN * HH];        // 16 MB : xs = x @ Win^T + b
__device__ float g_msgp[8 * NN * HH];       // split-K=4 partials of adj @ h_time, per dir
__device__ float g_H0[2][NN * HH];          // h_time / layer-2 output
__device__ float g_C0[2][NN * HH];
__device__ float g_H1[2][NN * HH];          // layer-1 output
__device__ float g_C1[2][NN * HH];
__device__ float g_v[2 * HH + 1];           // fused fc0/wout vector + scalar

__device__ __forceinline__ float sigm(float x) { return 1.0f / (1.0f + expf(-x)); }

__device__ __forceinline__ uint32_t f2tf(float f) {
    uint32_t u;
    asm("cvt.rna.tf32.f32 %0, %1;" : "=r"(u) : "f"(f));
    return u;
}

// D = A(16x8,row) * B(8x8 as [k][n]) + D, tf32 in, fp32 accum
__device__ __forceinline__ void mma8(float* c, uint32_t a0, uint32_t a1, uint32_t a2,
                                     uint32_t a3, uint32_t b0, uint32_t b1) {
    asm volatile(
        "mma.sync.aligned.m16n8k8.row.col.f32.tf32.tf32.f32 "
        "{%0,%1,%2,%3},{%4,%5,%6,%7},{%8,%9},{%0,%1,%2,%3};"
        : "+f"(c[0]), "+f"(c[1]), "+f"(c[2]), "+f"(c[3])
        : "r"(a0), "r"(a1), "r"(a2), "r"(a3), "r"(b0), "r"(b1));
}

// smem strides chosen for conflict-free fragment reads:
//  A frag read addr = m*20 + k  -> (gid*20 + t4) mod 32 all distinct
//  B frag read addr = k*136 + c -> (t4*136 + nt*8+gid) mod 32 all distinct
#define AS_STR 20
#define BS_STR 136

// ============================================================
// P1 (fp32, once): xs[t,n,h] = x[t,n,:] . Win_w[h,:] + Win_b[h]
// ============================================================
__global__ void k_xs(const float* __restrict__ x,
                     const float* __restrict__ Ww,
                     const float* __restrict__ Wb) {
    __shared__ float As[16][68];
    __shared__ float Bs[16][64];
    int tid = threadIdx.x;
    int tx = tid & 15, ty = tid >> 4;
    int m0 = blockIdx.y * 64;
    int n0 = blockIdx.x * 64;
    float acc[4][4] = {};
    int arow = tid >> 2;
    int akq  = (tid & 3) * 4;
    int bn   = tid & 63;
    int bkq  = (tid >> 6) * 4;
    for (int k0 = 0; k0 < FF; k0 += 16) {
        float4 av = *(const float4*)&x[(size_t)(m0 + arow) * FF + k0 + akq];
        As[akq + 0][arow] = av.x; As[akq + 1][arow] = av.y;
        As[akq + 2][arow] = av.z; As[akq + 3][arow] = av.w;
        float4 bv = *(const float4*)&Ww[(size_t)(n0 + bn) * FF + k0 + bkq];
        Bs[bkq + 0][bn] = bv.x; Bs[bkq + 1][bn] = bv.y;
        Bs[bkq + 2][bn] = bv.z; Bs[bkq + 3][bn] = bv.w;
        __syncthreads();
#pragma unroll
        for (int kk = 0; kk < 16; kk++) {
            float4 b4 = *(const float4*)&Bs[kk][tx * 4];
            float a0 = As[kk][ty * 4 + 0], a1 = As[kk][ty * 4 + 1];
            float a2 = As[kk][ty * 4 + 2], a3 = As[kk][ty * 4 + 3];
            acc[0][0] += a0 * b4.x; acc[0][1] += a0 * b4.y; acc[0][2] += a0 * b4.z; acc[0][3] += a0 * b4.w;
            acc[1][0] += a1 * b4.x; acc[1][1] += a1 * b4.y; acc[1][2] += a1 * b4.z; acc[1][3] += a1 * b4.w;
            acc[2][0] += a2 * b4.x; acc[2][1] += a2 * b4.y; acc[2][2] += a2 * b4.z; acc[2][3] += a2 * b4.w;
            acc[3][0] += a3 * b4.x; acc[3][1] += a3 * b4.y; acc[3][2] += a3 * b4.z; acc[3][3] += a3 * b4.w;
        }
        __syncthreads();
    }
#pragma unroll
    for (int r = 0; r < 4; r++) {
        int m = m0 + ty * 4 + r;
#pragma unroll
        for (int c = 0; c < 4; c++) {
            int n = n0 + tx * 4 + c;
            g_xs[(size_t)m * HH + n] = acc[r][c] + Wb[n];
        }
    }
}

// ============================================================
// init: H0 = C0 = first frame of each direction's sequence
// ============================================================
__global__ void k_init() {
    int i = blockIdx.x * blockDim.x + threadIdx.x;
    int d = i / (NN * HH);
    int r = i - d * (NN * HH);
    int t0 = d ? (TT - 1) : 0;
    float v = g_xs[(size_t)t0 * NN * HH + r];
    g_H0[d][r] = v;
    g_C0[d][r] = v;
}

// ============================================================
// prep: v[j] = wout_w . fc0_w[:,j] ;  v[256] = fused scalar bias
// ============================================================
__global__ void k_prep(const float* __restrict__ fc0w,
                       const float* __restrict__ fc0b,
                       const float* __restrict__ woutw,
                       const float* __restrict__ woutb) {
    int j = threadIdx.x;
    if (j < 2 * HH) {
        float s = 0.0f;
        for (int k = 0; k < HH; k++) s += woutw[k] * fc0w[(size_t)k * (2 * HH) + j];
        g_v[j] = s;
    } else if (j == 2 * HH) {
        float s = woutb[0];
        for (int k = 0; k < HH; k++) s += woutw[k] * fc0b[k];
        g_v[2 * HH] = s;
    }
}

// ============================================================
// k_msg (tf32 TC): partials of adj_t @ H0, split-K = 4 (256 each)
// C = 1024 x 128 per dir. tile 64x128, 4 warps (warp 16x128).
// grid (1, 16, 8): z = d*4 + split
// ============================================================
__global__ void __launch_bounds__(128, 8)
k_msg(const float* __restrict__ adjs, int s) {
    int z = blockIdx.z;
    int d = z >> 2, sp = z & 3;
    int tt = d ? (TT - 1 - s) : s;
    const float* __restrict__ A = adjs + (size_t)tt * NN * NN;
    const float* __restrict__ B = g_H0[d];
    __shared__ uint32_t As[64][AS_STR];
    __shared__ uint32_t Bs[16][BS_STR];
    int t = threadIdx.x;
    int w = t >> 5, lane = t & 31, gid = lane >> 2, t4 = lane & 3;
    int m0 = blockIdx.y * 64;
    float acc[16][4] = {};
    int kbeg = sp * 256;
    for (int k0 = kbeg; k0 < kbeg + 256; k0 += 16) {
#pragma unroll
        for (int p = 0; p < 2; p++) {
            int idx = p * 128 + t; int row = idx >> 2; int kq = (idx & 3) * 4;
            float4 v = *(const float4*)&A[(size_t)(m0 + row) * NN + k0 + kq];
            As[row][kq + 0] = f2tf(v.x); As[row][kq + 1] = f2tf(v.y);
            As[row][kq + 2] = f2tf(v.z); As[row][kq + 3] = f2tf(v.w);
        }
#pragma unroll
        for (int p = 0; p < 4; p++) {
            int idx = p * 128 + t; int kr = idx >> 5; int c0 = (idx & 31) * 4;
            float4 v = *(const float4*)&B[(size_t)(k0 + kr) * HH + c0];
            Bs[kr][c0 + 0] = f2tf(v.x); Bs[kr][c0 + 1] = f2tf(v.y);
            Bs[kr][c0 + 2] = f2tf(v.z); Bs[kr][c0 + 3] = f2tf(v.w);
        }
        __syncthreads();
#pragma unroll
        for (int kk = 0; kk < 16; kk += 8) {
            uint32_t a0 = As[w * 16 + gid][kk + t4];
            uint32_t a1 = As[w * 16 + gid + 8][kk + t4];
            uint32_t a2 = As[w * 16 + gid][kk + t4 + 4];
            uint32_t a3 = As[w * 16 + gid + 8][kk + t4 + 4];
#pragma unroll
            for (int nt = 0; nt < 16; nt++) {
                uint32_t b0 = Bs[kk + t4][nt * 8 + gid];
                uint32_t b1 = Bs[kk + t4 + 4][nt * 8 + gid];
                mma8(acc[nt], a0, a1, a2, a3, b0, b1);
            }
        }
        __syncthreads();
    }
    float* __restrict__ out = g_msgp + (size_t)z * NN * HH;
#pragma unroll
    for (int nt = 0; nt < 16; nt++)
#pragma unroll
        for (int r = 0; r < 2; r++)
#pragma unroll
            for (int e = 0; e < 2; e++) {
                int m = m0 + w * 16 + gid + r * 8;
                int c = nt * 8 + t4 * 2 + e;
                out[(size_t)m * HH + c] = acc[nt][r * 2 + e];
            }
}

// ============================================================
// k_layer (tf32 TC, fused cell):
//   z = [msg | h_in | xs_t] @ [Wn ; Wh ; Wx] + b     K = 384
// Gate-gathered B: block's 128 cols = 32 h-cols x 4 gates, so each
// thread owns all 4 gates of its (m, h) pairs -> cell in registers.
// tile 64x128, 4 warps. grid (4, 16, 2): x=h-block, y=m-block, z=dir
// layer 0: H0,C0 -> H1,C1 ; layer 1: H1,C1 -> H0,C0
// msg term always uses H0-at-step-start partials (g_msgp).
// ============================================================
__global__ void __launch_bounds__(128, 8)
k_layer(const float* __restrict__ fWn, const float* __restrict__ fWh,
        const float* __restrict__ fWx, const float* __restrict__ fb,
        const float* __restrict__ bWn, const float* __restrict__ bWh,
        const float* __restrict__ bWx, const float* __restrict__ bb,
        int s, int layer) {
    int d = blockIdx.z;
    int tt = d ? (TT - 1 - s) : s;
    const float* __restrict__ Wn  = d ? bWn : fWn;
    const float* __restrict__ Wh  = d ? bWh : fWh;
    const float* __restrict__ Wx  = d ? bWx : fWx;
    const float* __restrict__ bias = d ? bb : fb;
    const float* __restrict__ Hin = layer ? g_H1[d] : g_H0[d];
    const float* __restrict__ Cin = layer ? g_C1[d] : g_C0[d];
    float* __restrict__ Hout = layer ? g_H0[d] : g_H1[d];
    float* __restrict__ Cout = layer ? g_C0[d] : g_C1[d];
    const float* __restrict__ Xs = g_xs + (size_t)tt * NN * HH;
    const float* __restrict__ mp = g_msgp + (size_t)d * 4 * NN * HH;

    __shared__ uint32_t As[64][AS_STR];
    __shared__ uint32_t Bs[16][BS_STR];
    int t = threadIdx.x;
    int w = t >> 5, lane = t & 31, gid = lane >> 2, t4 = lane & 3;
    int m0 = blockIdx.y * 64;
    int bh = blockIdx.x * 32;
    float acc[16][4] = {};

    for (int k0 = 0; k0 < 384; k0 += 16) {
#pragma unroll
        for (int p = 0; p < 2; p++) {
            int idx = p * 128 + t; int row = idx >> 2; int kq = (idx & 3) * 4;
            float4 v;
            if (k0 < HH) {              // msg = sum of 4 split-K partials
                size_t off = (size_t)(m0 + row) * HH + k0 + kq;
                float4 v0 = *(const float4*)&mp[off];
                float4 v1 = *(const float4*)&mp[(size_t)NN * HH + off];
                float4 v2 = *(const float4*)&mp[(size_t)2 * NN * HH + off];
                float4 v3 = *(const float4*)&mp[(size_t)3 * NN * HH + off];
                v.x = (v0.x + v1.x) + (v2.x + v3.x);
                v.y = (v0.y + v1.y) + (v2.y + v3.y);
                v.z = (v0.z + v1.z) + (v2.z + v3.z);
                v.w = (v0.w + v1.w) + (v2.w + v3.w);
            } else if (k0 < 2 * HH) {   // recurrent h
                v = *(const float4*)&Hin[(size_t)(m0 + row) * HH + (k0 - HH) + kq];
            } else {                    // input xs_t
                v = *(const float4*)&Xs[(size_t)(m0 + row) * HH + (k0 - 2 * HH) + kq];
            }
            As[row][kq + 0] = f2tf(v.x); As[row][kq + 1] = f2tf(v.y);
            As[row][kq + 2] = f2tf(v.z); As[row][kq + 3] = f2tf(v.w);
        }
#pragma unroll
        for (int p = 0; p < 4; p++) {
            int idx = p * 128 + t; int kr = idx >> 5; int c0 = (idx & 31) * 4;
            int g = c0 >> 5, j0 = c0 & 31;
            const float* __restrict__ W =
                (k0 < HH)     ? (Wn + (size_t)(k0 + kr) * H4)
                : (k0 < 2*HH) ? (Wh + (size_t)(k0 - HH + kr) * H4)
                              : (Wx + (size_t)(k0 - 2 * HH + kr) * H4);
            float4 v = *(const float4*)&W[g * HH + bh + j0];
            Bs[kr][c0 + 0] = f2tf(v.x); Bs[kr][c0 + 1] = f2tf(v.y);
            Bs[kr][c0 + 2] = f2tf(v.z); Bs[kr][c0 + 3] = f2tf(v.w);
        }
        __syncthreads();
#pragma unroll
        for (int kk = 0; kk < 16; kk += 8) {
            uint32_t a0 = As[w * 16 + gid][kk + t4];
            uint32_t a1 = As[w * 16 + gid + 8][kk + t4];
            uint32_t a2 = As[w * 16 + gid][kk + t4 + 4];
            uint32_t a3 = As[w * 16 + gid + 8][kk + t4 + 4];
#pragma unroll
            for (int nt = 0; nt < 16; nt++) {
                uint32_t b0 = Bs[kk + t4][nt * 8 + gid];
                uint32_t b1 = Bs[kk + t4 + 4][nt * 8 + gid];
                mma8(acc[nt], a0, a1, a2, a3, b0, b1);
            }
        }
        __syncthreads();
    }

    // fused LSTM cell epilogue: acc[g*4+q][r*2+e] = z-part for gate g,
    // h-col = bh + q*8 + t4*2 + e, row m = m0 + w*16 + gid + r*8
#pragma unroll
    for (int r = 0; r < 2; r++) {
        int m = m0 + w * 16 + gid + r * 8;
#pragma unroll
        for (int q = 0; q < 4; q++) {
#pragma unroll
            for (int e = 0; e < 2; e++) {
                int hcol = bh + q * 8 + t4 * 2 + e;
                int ci = r * 2 + e;
                float zi = acc[0 * 4 + q][ci] + bias[0 * HH + hcol];
                float zf = acc[1 * 4 + q][ci] + bias[1 * HH + hcol];
                float zo = acc[2 * 4 + q][ci] + bias[2 * HH + hcol];
                float zg = acc[3 * 4 + q][ci] + bias[3 * HH + hcol];
                float c_old = Cin[(size_t)m * HH + hcol];
                float c2 = sigm(zf) * c_old + sigm(zi) * tanhf(zg);
                float h2 = sigm(zo) * tanhf(c2);
                Cout[(size_t)m * HH + hcol] = c2;
                Hout[(size_t)m * HH + hcol] = h2;
            }
        }
    }
}

// ============================================================
// final: y[n] = [h_f | h_b][n] . v + v[256]
// ============================================================
__global__ void k_final(float* __restrict__ out) {
    int warp = threadIdx.x >> 5;
    int lane = threadIdx.x & 31;
    int n = blockIdx.x * 8 + warp;
    float s = 0.0f;
#pragma unroll
    for (int j = lane; j < 2 * HH; j += 32) {
        float hv = (j < HH) ? g_H0[0][(size_t)n * HH + j]
                            : g_H0[1][(size_t)n * HH + (j - HH)];
        s += hv * g_v[j];
    }
#pragma unroll
    for (int o = 16; o > 0; o >>= 1) s += __shfl_down_sync(0xffffffffu, s, o);
    if (lane == 0) out[n] = s + g_v[2 * HH];
}

// ============================================================
extern "C" void kernel_launch(void* const* d_in, const int* in_sizes, int n_in,
                              void* d_out, int out_size) {
    const float* x     = (const float*)d_in[0];
    const float* adjs  = (const float*)d_in[1];
    const float* Winw  = (const float*)d_in[3];
    const float* Winb  = (const float*)d_in[4];
    const float* fWx   = (const float*)d_in[5];
    const float* fWh   = (const float*)d_in[6];
    const float* fWn   = (const float*)d_in[7];
    const float* fb    = (const float*)d_in[8];
    const float* bWx   = (const float*)d_in[9];
    const float* bWh   = (const float*)d_in[10];
    const float* bWn   = (const float*)d_in[11];
    const float* bb    = (const float*)d_in[12];
    const float* fc0w  = (const float*)d_in[13];
    const float* fc0b  = (const float*)d_in[14];
    const float* woutw = (const float*)d_in[15];
    const float* woutb = (const float*)d_in[16];
    float* out = (float*)d_out;

    k_xs<<<dim3(2, 512), 256>>>(x, Winw, Winb);
    k_prep<<<1, 288>>>(fc0w, fc0b, woutw, woutb);
    k_init<<<(2 * NN * HH) / 256, 256>>>();

    for (int s = 0; s < TT; s++) {
        k_msg<<<dim3(1, 16, 8), 128>>>(adjs, s);
        k_layer<<<dim3(4, 16, 2), 128>>>(fWn, fWh, fWx, fb, bWn, bWh, bWx, bb, s, 0);
        k_layer<<<dim3(4, 16, 2), 128>>>(fWn, fWh, fWx, fb, bWn, bWh, bWx, bb, s, 1);
    }

    k_final<<<NN / 8, 256>>>(out);
}

// round 5
// speedup vs baseline: 3.3210x; 3.3210x over previous
#include <cuda_runtime.h>
#include <math.h>
#include <stdint.h>

#define TT 32
#define NN 1024
#define FF 64
#define HH 128
#define H4 512

// ---- scratch (static __device__ arrays; no runtime allocation) ----
__device__ float    g_xs[TT * NN * HH];        // fp32 xs (for init / reference frame)
__device__ uint32_t g_xs_tf[TT * NN * HH];     // tf32 xs (MMA operand)
__device__ float    g_msgp[8][NN * HH];        // split-K=4 partials per dir
__device__ uint32_t g_msg_tf[2][NN * HH];      // summed msg, tf32 (MMA operand)
__device__ float    g_H0f[2][NN * HH];         // h_time fp32 (for k_final)
__device__ uint32_t g_H0tf[2][NN * HH];        // h_time tf32
__device__ uint32_t g_H1tf[2][NN * HH];        // layer-1 h tf32
__device__ float    g_C0[2][NN * HH];
__device__ float    g_C1[2][NN * HH];
__device__ uint32_t g_W[2][384 * 512];         // pre-gathered tf32 [Wn;Wh;Wx]
__device__ float    g_v[2 * HH + 1];           // fused fc0/wout vector + scalar
__device__ unsigned g_cnt[2][16];              // split-K completion counters

__device__ __forceinline__ float sigm(float x) { return 1.0f / (1.0f + expf(-x)); }

__device__ __forceinline__ uint32_t f2tf(float f) {
    uint32_t u;
    asm("cvt.rna.tf32.f32 %0, %1;" : "=r"(u) : "f"(f));
    return u;
}

__device__ __forceinline__ void mma8(float* c, uint32_t a0, uint32_t a1, uint32_t a2,
                                     uint32_t a3, uint32_t b0, uint32_t b1) {
    asm volatile(
        "mma.sync.aligned.m16n8k8.row.col.f32.tf32.tf32.f32 "
        "{%0,%1,%2,%3},{%4,%5,%6,%7},{%8,%9},{%0,%1,%2,%3};"
        : "+f"(c[0]), "+f"(c[1]), "+f"(c[2]), "+f"(c[3])
        : "r"(a0), "r"(a1), "r"(a2), "r"(a3), "r"(b0), "r"(b1));
}

__device__ __forceinline__ void cpa16(uint32_t dst, const void* src) {
    asm volatile("cp.async.cg.shared.global [%0], [%1], 16;" :: "r"(dst), "l"(src));
}
__device__ __forceinline__ void cp_commit() { asm volatile("cp.async.commit_group;"); }
__device__ __forceinline__ void cp_wait1()  { asm volatile("cp.async.wait_group 1;" ::: "memory"); }
__device__ __forceinline__ uint32_t s2u(const void* p) {
    return (uint32_t)__cvta_generic_to_shared(p);
}

// smem strides (uint32 units), conflict-free for fragment reads:
//  A: addr = m*20 + k  -> per-lane (gid*20 + t4) mod 32 all distinct
//  B: addr = k*136 + c -> per-lane (t4*136 + nt*8 + gid) ≡ 8*t4+gid distinct
#define AS_STR 20
#define BS_STR 136

// ============================================================
// k_xs (fp32, once): xs = x @ Win^T + b ; writes fp32 + tf32 copies
// ============================================================
__global__ void k_xs(const float* __restrict__ x,
                     const float* __restrict__ Ww,
                     const float* __restrict__ Wb) {
    __shared__ float As[16][68];
    __shared__ float Bs[16][64];
    int tid = threadIdx.x;
    int tx = tid & 15, ty = tid >> 4;
    int m0 = blockIdx.y * 64;
    int n0 = blockIdx.x * 64;
    float acc[4][4] = {};
    int arow = tid >> 2;
    int akq  = (tid & 3) * 4;
    int bn   = tid & 63;
    int bkq  = (tid >> 6) * 4;
    for (int k0 = 0; k0 < FF; k0 += 16) {
        float4 av = *(const float4*)&x[(size_t)(m0 + arow) * FF + k0 + akq];
        As[akq + 0][arow] = av.x; As[akq + 1][arow] = av.y;
        As[akq + 2][arow] = av.z; As[akq + 3][arow] = av.w;
        float4 bv = *(const float4*)&Ww[(size_t)(n0 + bn) * FF + k0 + bkq];
        Bs[bkq + 0][bn] = bv.x; Bs[bkq + 1][bn] = bv.y;
        Bs[bkq + 2][bn] = bv.z; Bs[bkq + 3][bn] = bv.w;
        __syncthreads();
#pragma unroll
        for (int kk = 0; kk < 16; kk++) {
            float4 b4 = *(const float4*)&Bs[kk][tx * 4];
            float a0 = As[kk][ty * 4 + 0], a1 = As[kk][ty * 4 + 1];
            float a2 = As[kk][ty * 4 + 2], a3 = As[kk][ty * 4 + 3];
            acc[0][0] += a0 * b4.x; acc[0][1] += a0 * b4.y; acc[0][2] += a0 * b4.z; acc[0][3] += a0 * b4.w;
            acc[1][0] += a1 * b4.x; acc[1][1] += a1 * b4.y; acc[1][2] += a1 * b4.z; acc[1][3] += a1 * b4.w;
            acc[2][0] += a2 * b4.x; acc[2][1] += a2 * b4.y; acc[2][2] += a2 * b4.z; acc[2][3] += a2 * b4.w;
            acc[3][0] += a3 * b4.x; acc[3][1] += a3 * b4.y; acc[3][2] += a3 * b4.z; acc[3][3] += a3 * b4.w;
        }
        __syncthreads();
    }
#pragma unroll
    for (int r = 0; r < 4; r++) {
        int m = m0 + ty * 4 + r;
#pragma unroll
        for (int c = 0; c < 4; c++) {
            int n = n0 + tx * 4 + c;
            float v = acc[r][c] + Wb[n];
            g_xs[(size_t)m * HH + n] = v;
            g_xs_tf[(size_t)m * HH + n] = f2tf(v);
        }
    }
}

// ============================================================
// k_wprep (once): gate-gathered tf32 weight cat [Wn;Wh;Wx] per dir
// gathered col c: b=c>>7, c'=c&127, nt=c'>>3, wi=c'&7,
//                 g=nt&3, j=((nt>>2)<<3)+wi, src col = g*128 + b*32 + j
// ============================================================
__global__ void k_wprep(const float* __restrict__ fWn, const float* __restrict__ fWh,
                        const float* __restrict__ fWx,
                        const float* __restrict__ bWn, const float* __restrict__ bWh,
                        const float* __restrict__ bWx) {
    int i = blockIdx.x * blockDim.x + threadIdx.x;
    if (i >= 2 * 384 * 512) return;
    int d = i / (384 * 512);
    int rem = i - d * (384 * 512);
    int k = rem >> 9;
    int c = rem & 511;
    int b = c >> 7, cl = c & 127, nt = cl >> 3, wi = cl & 7;
    int g = nt & 3, j = ((nt >> 2) << 3) + wi;
    int srccol = g * HH + b * 32 + j;
    const float* W; int kr;
    if (k < 128)      { W = d ? bWn : fWn; kr = k; }
    else if (k < 256) { W = d ? bWh : fWh; kr = k - 128; }
    else              { W = d ? bWx : fWx; kr = k - 256; }
    g_W[d][rem] = f2tf(W[(size_t)kr * H4 + srccol]);
}

// ============================================================
// k_init: H0 = C0 = first frame (fp32 + tf32); zero counters
// ============================================================
__global__ void k_init() {
    int i = blockIdx.x * blockDim.x + threadIdx.x;
    if (i < 32) ((unsigned*)g_cnt)[i] = 0u;
    int d = i / (NN * HH);
    int r = i - d * (NN * HH);
    int t0 = d ? (TT - 1) : 0;
    float v = g_xs[(size_t)t0 * NN * HH + r];
    g_H0f[d][r] = v;
    g_H0tf[d][r] = f2tf(v);
    g_C0[d][r] = v;
}

// ============================================================
// k_prep: v[j] = wout_w . fc0_w[:,j] ;  v[256] = fused scalar bias
// ============================================================
__global__ void k_prep(const float* __restrict__ fc0w,
                       const float* __restrict__ fc0b,
                       const float* __restrict__ woutw,
                       const float* __restrict__ woutb) {
    int j = threadIdx.x;
    if (j < 2 * HH) {
        float s = 0.0f;
        for (int k = 0; k < HH; k++) s += woutw[k] * fc0w[(size_t)k * (2 * HH) + j];
        g_v[j] = s;
    } else if (j == 2 * HH) {
        float s = woutb[0];
        for (int k = 0; k < HH; k++) s += woutw[k] * fc0b[k];
        g_v[2 * HH] = s;
    }
}

// ============================================================
// k_msg: adj_t @ H0 (tf32 TC), split-K=4, cp.async double-buffered.
// 256 thr (8 warps), block tile 64x128, warp 16x64.
// grid (4 splits, 16 m, 2 dir). Last block per (d,m) sums 4 partials
// -> g_msg_tf (threadfence-reduction pattern; counter monotone/step).
// ============================================================
__global__ void __launch_bounds__(256, 2)
k_msg(const float* __restrict__ adjs, int s) {
    int sp = blockIdx.x, mb = blockIdx.y, d = blockIdx.z;
    int tt = d ? (TT - 1 - s) : s;
    const float* __restrict__ A = adjs + (size_t)tt * NN * NN;
    const uint32_t* __restrict__ B = g_H0tf[d];

    __shared__ uint32_t As[2][64 * AS_STR];
    __shared__ uint32_t Bs[2][16 * BS_STR];
    __shared__ int s_last;

    int t = threadIdx.x, w = t >> 5, lane = t & 31, gid = lane >> 2, t4 = lane & 3;
    int wm = (w >> 1) * 16, wn = (w & 1) * 64;
    int m0 = mb * 64;
    int kbeg = sp * 256;
    float acc[8][4] = {};

    int arow = t >> 2, apart = (t & 3) * 4;   // A chunk: 1 per thread
    const int NIT = 16;

    auto issue = [&](int it) {
        int st = it & 1;
        int k0 = kbeg + it * 16;
        cpa16(s2u(&As[st][arow * AS_STR + apart]),
              &A[(size_t)(m0 + arow) * NN + k0 + apart]);
#pragma unroll
        for (int j2 = 0; j2 < 2; j2++) {
            int idx = t + 256 * j2;
            int br = idx >> 5, pc = (idx & 31) * 4;
            cpa16(s2u(&Bs[st][br * BS_STR + pc]),
                  &B[(size_t)(k0 + br) * HH + pc]);
        }
    };

    issue(0); cp_commit();
    issue(1); cp_commit();

    for (int it = 0; it < NIT; it++) {
        cp_wait1();
        __syncthreads();
        int st = it & 1;
#pragma unroll
        for (int kk = 0; kk < 16; kk += 8) {
            uint32_t a0 = f2tf(__uint_as_float(As[st][(wm + gid) * AS_STR + kk + t4]));
            uint32_t a1 = f2tf(__uint_as_float(As[st][(wm + gid + 8) * AS_STR + kk + t4]));
            uint32_t a2 = f2tf(__uint_as_float(As[st][(wm + gid) * AS_STR + kk + t4 + 4]));
            uint32_t a3 = f2tf(__uint_as_float(As[st][(wm + gid + 8) * AS_STR + kk + t4 + 4]));
#pragma unroll
            for (int nt = 0; nt < 8; nt++) {
                uint32_t b0 = Bs[st][(kk + t4) * BS_STR + wn + nt * 8 + gid];
                uint32_t b1 = Bs[st][(kk + t4 + 4) * BS_STR + wn + nt * 8 + gid];
                mma8(acc[nt], a0, a1, a2, a3, b0, b1);
            }
        }
        __syncthreads();
        if (it + 2 < NIT) issue(it + 2);
        cp_commit();
    }

    // write split partial
    float* __restrict__ P = g_msgp[d * 4 + sp];
#pragma unroll
    for (int nt = 0; nt < 8; nt++)
#pragma unroll
        for (int r = 0; r < 2; r++)
#pragma unroll
            for (int e = 0; e < 2; e++) {
                int m = m0 + wm + gid + r * 8;
                int c = wn + nt * 8 + t4 * 2 + e;
                P[(size_t)m * HH + c] = acc[nt][r * 2 + e];
            }
    __threadfence();
    __syncthreads();
    if (t == 0) {
        unsigned old = atomicAdd(&g_cnt[d][mb], 1u);
        s_last = ((old & 3u) == 3u);
    }
    __syncthreads();
    if (s_last) {
        __threadfence();
        const float* __restrict__ P0 = g_msgp[d * 4 + 0];
        const float* __restrict__ P1 = g_msgp[d * 4 + 1];
        const float* __restrict__ P2 = g_msgp[d * 4 + 2];
        const float* __restrict__ P3 = g_msgp[d * 4 + 3];
        uint32_t* __restrict__ O = g_msg_tf[d];
#pragma unroll
        for (int i = t * 4; i < 64 * HH; i += 1024) {
            size_t off = (size_t)(m0 + (i >> 7)) * HH + (i & 127);
            float4 v0 = *(const float4*)&P0[off];
            float4 v1 = *(const float4*)&P1[off];
            float4 v2 = *(const float4*)&P2[off];
            float4 v3 = *(const float4*)&P3[off];
            uint4 o;
            o.x = f2tf((v0.x + v1.x) + (v2.x + v3.x));
            o.y = f2tf((v0.y + v1.y) + (v2.y + v3.y));
            o.z = f2tf((v0.z + v1.z) + (v2.z + v3.z));
            o.w = f2tf((v0.w + v1.w) + (v2.w + v3.w));
            *(uint4*)&O[off] = o;
        }
    }
}

// ============================================================
// k_layer: z = [msg | h_in | xs_t] @ Wcat (K=384, tf32 TC, pre-gathered
// gate-interleaved B) + fused LSTM cell. 256 thr, tile 64x128, warp 16x64.
// grid (4 h-blocks, 16 m, 2 dir).
// layer 0: H0,C0 -> H1,C1 ; layer 1: H1,C1 -> H0,C0 (+fp32 H0 copy)
// ============================================================
__global__ void __launch_bounds__(256, 2)
k_layer(const float* __restrict__ fb, const float* __restrict__ bb,
        int s, int layer) {
    int bh = blockIdx.x, mb = blockIdx.y, d = blockIdx.z;
    int tt = d ? (TT - 1 - s) : s;
    const uint32_t* __restrict__ Am = g_msg_tf[d];
    const uint32_t* __restrict__ Ah = layer ? g_H1tf[d] : g_H0tf[d];
    const uint32_t* __restrict__ Ax = g_xs_tf + (size_t)tt * NN * HH;
    const uint32_t* __restrict__ Wg = g_W[d];
    const float* __restrict__ bias = d ? bb : fb;
    const float* __restrict__ Cin  = layer ? g_C1[d] : g_C0[d];
    float* __restrict__ Cout = layer ? g_C0[d] : g_C1[d];
    uint32_t* __restrict__ HoutTf = layer ? g_H0tf[d] : g_H1tf[d];
    float* __restrict__ HoutF = g_H0f[d];   // only written when layer==1

    __shared__ uint32_t As[2][64 * AS_STR];
    __shared__ uint32_t Bs[2][16 * BS_STR];

    int t = threadIdx.x, w = t >> 5, lane = t & 31, gid = lane >> 2, t4 = lane & 3;
    int wm = (w >> 1) * 16, wn = (w & 1) * 64;
    int m0 = mb * 64;
    float acc[8][4] = {};

    int arow = t >> 2, apart = (t & 3) * 4;
    const int NIT = 24;

    auto issue = [&](int it) {
        int st = it & 1;
        int k0 = it * 16;
        const uint32_t* Abase; int ko;
        if (k0 < 128)      { Abase = Am; ko = k0; }
        else if (k0 < 256) { Abase = Ah; ko = k0 - 128; }
        else               { Abase = Ax; ko = k0 - 256; }
        cpa16(s2u(&As[st][arow * AS_STR + apart]),
              &Abase[(size_t)(m0 + arow) * HH + ko + apart]);
#pragma unroll
        for (int j2 = 0; j2 < 2; j2++) {
            int idx = t + 256 * j2;
            int br = idx >> 5, pc = (idx & 31) * 4;
            cpa16(s2u(&Bs[st][br * BS_STR + pc]),
                  &Wg[(size_t)(k0 + br) * 512 + bh * 128 + pc]);
        }
    };

    issue(0); cp_commit();
    issue(1); cp_commit();

    for (int it = 0; it < NIT; it++) {
        cp_wait1();
        __syncthreads();
        int st = it & 1;
#pragma unroll
        for (int kk = 0; kk < 16; kk += 8) {
            uint32_t a0 = As[st][(wm + gid) * AS_STR + kk + t4];
            uint32_t a1 = As[st][(wm + gid + 8) * AS_STR + kk + t4];
            uint32_t a2 = As[st][(wm + gid) * AS_STR + kk + t4 + 4];
            uint32_t a3 = As[st][(wm + gid + 8) * AS_STR + kk + t4 + 4];
#pragma unroll
            for (int nt = 0; nt < 8; nt++) {
                uint32_t b0 = Bs[st][(kk + t4) * BS_STR + wn + nt * 8 + gid];
                uint32_t b1 = Bs[st][(kk + t4 + 4) * BS_STR + wn + nt * 8 + gid];
                mma8(acc[nt], a0, a1, a2, a3, b0, b1);
            }
        }
        __syncthreads();
        if (it + 2 < NIT) issue(it + 2);
        cp_commit();
    }

    // fused cell: thread owns all 4 gates of 8 (m,h) cells.
    // acc[nt][r*2+e]: gate g = nt&3, jgrp = nt>>2;
    // h = bh*32 + (w&1)*16 + jgrp*8 + t4*2 + e; m = m0 + wm + gid + r*8
#pragma unroll
    for (int r = 0; r < 2; r++) {
        int m = m0 + wm + gid + r * 8;
#pragma unroll
        for (int jg = 0; jg < 2; jg++) {
#pragma unroll
            for (int e = 0; e < 2; e++) {
                int h = bh * 32 + (w & 1) * 16 + jg * 8 + t4 * 2 + e;
                int ci = r * 2 + e;
                float zi = acc[jg * 4 + 0][ci] + bias[0 * HH + h];
                float zf = acc[jg * 4 + 1][ci] + bias[1 * HH + h];
                float zo = acc[jg * 4 + 2][ci] + bias[2 * HH + h];
                float zg = acc[jg * 4 + 3][ci] + bias[3 * HH + h];
                float c_old = Cin[(size_t)m * HH + h];
                float c2 = sigm(zf) * c_old + sigm(zi) * tanhf(zg);
                float h2 = sigm(zo) * tanhf(c2);
                Cout[(size_t)m * HH + h] = c2;
                HoutTf[(size_t)m * HH + h] = f2tf(h2);
                if (layer) HoutF[(size_t)m * HH + h] = h2;
            }
        }
    }
}

// ============================================================
// final: y[n] = [h_f | h_b][n] . v + v[256]
// ============================================================
__global__ void k_final(float* __restrict__ out) {
    int warp = threadIdx.x >> 5;
    int lane = threadIdx.x & 31;
    int n = blockIdx.x * 8 + warp;
    float s = 0.0f;
#pragma unroll
    for (int j = lane; j < 2 * HH; j += 32) {
        float hv = (j < HH) ? g_H0f[0][(size_t)n * HH + j]
                            : g_H0f[1][(size_t)n * HH + (j - HH)];
        s += hv * g_v[j];
    }
#pragma unroll
    for (int o = 16; o > 0; o >>= 1) s += __shfl_down_sync(0xffffffffu, s, o);
    if (lane == 0) out[n] = s + g_v[2 * HH];
}

// ============================================================
extern "C" void kernel_launch(void* const* d_in, const int* in_sizes, int n_in,
                              void* d_out, int out_size) {
    const float* x     = (const float*)d_in[0];
    const float* adjs  = (const float*)d_in[1];
    const float* Winw  = (const float*)d_in[3];
    const float* Winb  = (const float*)d_in[4];
    const float* fWx   = (const float*)d_in[5];
    const float* fWh   = (const float*)d_in[6];
    const float* fWn   = (const float*)d_in[7];
    const float* fb    = (const float*)d_in[8];
    const float* bWx   = (const float*)d_in[9];
    const float* bWh   = (const float*)d_in[10];
    const float* bWn   = (const float*)d_in[11];
    const float* bb    = (const float*)d_in[12];
    const float* fc0w  = (const float*)d_in[13];
    const float* fc0b  = (const float*)d_in[14];
    const float* woutw = (const float*)d_in[15];
    const float* woutb = (const float*)d_in[16];
    float* out = (float*)d_out;

    k_xs<<<dim3(2, 512), 256>>>(x, Winw, Winb);
    k_prep<<<1, 288>>>(fc0w, fc0b, woutw, woutb);
    k_wprep<<<(2 * 384 * 512 + 255) / 256, 256>>>(fWn, fWh, fWx, bWn, bWh, bWx);
    k_init<<<(2 * NN * HH) / 256, 256>>>();

    for (int s = 0; s < TT; s++) {
        k_msg<<<dim3(4, 16, 2), 256>>>(adjs, s);
        k_layer<<<dim3(4, 16, 2), 256>>>(fb, bb, s, 0);
        k_layer<<<dim3(4, 16, 2), 256>>>(fb, bb, s, 1);
    }

    k_final<<<NN / 8, 256>>>(out);
}

// round 7
// speedup vs baseline: 3.4549x; 1.0403x over previous
#include <cuda_runtime.h>
#include <math.h>
#include <stdint.h>

#define TT 32
#define NN 1024
#define FF 64
#define HH 128
#define H4 512
#define NB 128          // persistent grid size (<=148 SMs, all co-resident)

// ---- scratch (static __device__ arrays; no runtime allocation) ----
__device__ float    g_xs[TT * NN * HH];        // fp32 xs
__device__ uint32_t g_xs_tf[TT * NN * HH];     // tf32 xs
__device__ float    g_msgp[8][NN * HH];        // split-K=4 partials per dir
__device__ uint32_t g_msg_tf[2][NN * HH];      // summed msg, tf32
__device__ float    g_H0f[2][NN * HH];         // final h_time fp32 (k_final)
__device__ uint32_t g_H0tf[2][NN * HH];        // h_time tf32
__device__ uint32_t g_H1tf[2][NN * HH];        // layer-1 h tf32
__device__ float    g_C0[2][NN * HH];
__device__ float    g_C1[2][NN * HH];
__device__ uint32_t g_W[2][384 * 512];         // pre-gathered tf32 [Wn;Wh;Wx]
__device__ float    g_v[2 * HH + 1];
__device__ unsigned g_cnt[2][16];              // split-K completion counters
__device__ unsigned g_arrive;                  // grid-barrier arrival counter

__device__ __forceinline__ float sigm(float x) { return 1.0f / (1.0f + expf(-x)); }

__device__ __forceinline__ uint32_t f2tf(float f) {
    uint32_t u;
    asm("cvt.rna.tf32.f32 %0, %1;" : "=r"(u) : "f"(f));
    return u;
}

__device__ __forceinline__ void mma8(float* c, uint32_t a0, uint32_t a1, uint32_t a2,
                                     uint32_t a3, uint32_t b0, uint32_t b1) {
    asm volatile(
        "mma.sync.aligned.m16n8k8.row.col.f32.tf32.tf32.f32 "
        "{%0,%1,%2,%3},{%4,%5,%6,%7},{%8,%9},{%0,%1,%2,%3};"
        : "+f"(c[0]), "+f"(c[1]), "+f"(c[2]), "+f"(c[3])
        : "r"(a0), "r"(a1), "r"(a2), "r"(a3), "r"(b0), "r"(b1));
}

__device__ __forceinline__ void cpa16(uint32_t dst, const void* src) {
    asm volatile("cp.async.cg.shared.global [%0], [%1], 16;" :: "r"(dst), "l"(src));
}
__device__ __forceinline__ void cp_commit() { asm volatile("cp.async.commit_group;"); }
__device__ __forceinline__ void cp_wait1()  { asm volatile("cp.async.wait_group 1;" ::: "memory"); }
__device__ __forceinline__ uint32_t s2u(const void* p) {
    return (uint32_t)__cvta_generic_to_shared(p);
}

// grid-wide barrier: monotone counter, reset by k_init each graph replay.
__device__ __forceinline__ void grid_bar(unsigned target) {
    __syncthreads();
    if (threadIdx.x == 0) {
        __threadfence();
        atomicAdd(&g_arrive, 1u);
        unsigned v;
        do {
            asm volatile("ld.acquire.gpu.global.u32 %0, [%1];"
                         : "=r"(v) : "l"(&g_arrive));
            if (v < target) __nanosleep(64);
        } while (v < target);
    }
    __syncthreads();
}

// smem strides (uint32 units), conflict-free fragment reads
#define AS_STR 20
#define BS_STR 136
#define AS_SZ (64 * AS_STR)
#define BS_SZ (16 * BS_STR)

// ============================================================
// k_xs (fp32, once): xs = x @ Win^T + b ; fp32 + tf32 copies
// ============================================================
__global__ void k_xs(const float* __restrict__ x,
                     const float* __restrict__ Ww,
                     const float* __restrict__ Wb) {
    __shared__ float As[16][68];
    __shared__ float Bs[16][64];
    int tid = threadIdx.x;
    int tx = tid & 15, ty = tid >> 4;
    int m0 = blockIdx.y * 64;
    int n0 = blockIdx.x * 64;
    float acc[4][4] = {};
    int arow = tid >> 2;
    int akq  = (tid & 3) * 4;
    int bn   = tid & 63;
    int bkq  = (tid >> 6) * 4;
    for (int k0 = 0; k0 < FF; k0 += 16) {
        float4 av = *(const float4*)&x[(size_t)(m0 + arow) * FF + k0 + akq];
        As[akq + 0][arow] = av.x; As[akq + 1][arow] = av.y;
        As[akq + 2][arow] = av.z; As[akq + 3][arow] = av.w;
        float4 bv = *(const float4*)&Ww[(size_t)(n0 + bn) * FF + k0 + bkq];
        Bs[bkq + 0][bn] = bv.x; Bs[bkq + 1][bn] = bv.y;
        Bs[bkq + 2][bn] = bv.z; Bs[bkq + 3][bn] = bv.w;
        __syncthreads();
#pragma unroll
        for (int kk = 0; kk < 16; kk++) {
            float4 b4 = *(const float4*)&Bs[kk][tx * 4];
            float a0 = As[kk][ty * 4 + 0], a1 = As[kk][ty * 4 + 1];
            float a2 = As[kk][ty * 4 + 2], a3 = As[kk][ty * 4 + 3];
            acc[0][0] += a0 * b4.x; acc[0][1] += a0 * b4.y; acc[0][2] += a0 * b4.z; acc[0][3] += a0 * b4.w;
            acc[1][0] += a1 * b4.x; acc[1][1] += a1 * b4.y; acc[1][2] += a1 * b4.z; acc[1][3] += a1 * b4.w;
            acc[2][0] += a2 * b4.x; acc[2][1] += a2 * b4.y; acc[2][2] += a2 * b4.z; acc[2][3] += a2 * b4.w;
            acc[3][0] += a3 * b4.x; acc[3][1] += a3 * b4.y; acc[3][2] += a3 * b4.z; acc[3][3] += a3 * b4.w;
        }
        __syncthreads();
    }
#pragma unroll
    for (int r = 0; r < 4; r++) {
        int m = m0 + ty * 4 + r;
#pragma unroll
        for (int c = 0; c < 4; c++) {
            int n = n0 + tx * 4 + c;
            float v = acc[r][c] + Wb[n];
            g_xs[(size_t)m * HH + n] = v;
            g_xs_tf[(size_t)m * HH + n] = f2tf(v);
        }
    }
}

// ============================================================
// k_wprep (once): gate-gathered tf32 weight cat [Wn;Wh;Wx] per dir
// ============================================================
__global__ void k_wprep(const float* __restrict__ fWn, const float* __restrict__ fWh,
                        const float* __restrict__ fWx,
                        const float* __restrict__ bWn, const float* __restrict__ bWh,
                        const float* __restrict__ bWx) {
    int i = blockIdx.x * blockDim.x + threadIdx.x;
    if (i >= 2 * 384 * 512) return;
    int d = i / (384 * 512);
    int rem = i - d * (384 * 512);
    int k = rem >> 9;
    int c = rem & 511;
    int b = c >> 7, cl = c & 127, nt = cl >> 3, wi = cl & 7;
    int g = nt & 3, j = ((nt >> 2) << 3) + wi;
    int srccol = g * HH + b * 32 + j;
    const float* W; int kr;
    if (k < 128)      { W = d ? bWn : fWn; kr = k; }
    else if (k < 256) { W = d ? bWh : fWh; kr = k - 128; }
    else              { W = d ? bWx : fWx; kr = k - 256; }
    g_W[d][rem] = f2tf(W[(size_t)kr * H4 + srccol]);
}

// ============================================================
// k_init: H0 = C0 = first frame; reset barrier + split-K counters
// ============================================================
__global__ void k_init() {
    int i = blockIdx.x * blockDim.x + threadIdx.x;
    if (i == 0) g_arrive = 0u;
    if (i < 32) ((unsigned*)g_cnt)[i] = 0u;
    int d = i / (NN * HH);
    int r = i - d * (NN * HH);
    int t0 = d ? (TT - 1) : 0;
    float v = g_xs[(size_t)t0 * NN * HH + r];
    g_H0tf[d][r] = f2tf(v);
    g_C0[d][r] = v;
}

// ============================================================
// k_prep: v[j] = wout_w . fc0_w[:,j] ;  v[256] = fused scalar bias
// ============================================================
__global__ void k_prep(const float* __restrict__ fc0w,
                       const float* __restrict__ fc0b,
                       const float* __restrict__ woutw,
                       const float* __restrict__ woutb) {
    int j = threadIdx.x;
    if (j < 2 * HH) {
        float s = 0.0f;
        for (int k = 0; k < HH; k++) s += woutw[k] * fc0w[(size_t)k * (2 * HH) + j];
        g_v[j] = s;
    } else if (j == 2 * HH) {
        float s = woutb[0];
        for (int k = 0; k < HH; k++) s += woutw[k] * fc0b[k];
        g_v[2 * HH] = s;
    }
}

// ============================================================
// msg tile: split sp of adj_t @ H0tf -> g_msgp; last block per (d,mb)
// sums 4 partials -> g_msg_tf. block tile 64x128, warp 16x64.
// ============================================================
__device__ __forceinline__ void msg_tile(const float* __restrict__ adjs, int s,
                                         int sp, int mb, int d,
                                         uint32_t* As, uint32_t* Bs, int* s_last) {
    int tt = d ? (TT - 1 - s) : s;
    const float* __restrict__ A = adjs + (size_t)tt * NN * NN;
    const uint32_t* __restrict__ B = g_H0tf[d];

    int t = threadIdx.x, w = t >> 5, lane = t & 31, gid = lane >> 2, t4 = lane & 3;
    int wm = (w >> 1) * 16, wn = (w & 1) * 64;
    int m0 = mb * 64;
    int kbeg = sp * 256;
    float acc[8][4] = {};
    int arow = t >> 2, apart = (t & 3) * 4;
    const int NIT = 16;

    auto issue = [&](int it) {
        int st = it & 1;
        int k0 = kbeg + it * 16;
        cpa16(s2u(&As[st * AS_SZ + arow * AS_STR + apart]),
              &A[(size_t)(m0 + arow) * NN + k0 + apart]);
#pragma unroll
        for (int j2 = 0; j2 < 2; j2++) {
            int idx = t + 256 * j2;
            int br = idx >> 5, pc = (idx & 31) * 4;
            cpa16(s2u(&Bs[st * BS_SZ + br * BS_STR + pc]),
                  &B[(size_t)(k0 + br) * HH + pc]);
        }
    };

    issue(0); cp_commit();
    issue(1); cp_commit();

    for (int it = 0; it < NIT; it++) {
        cp_wait1();
        __syncthreads();
        int st = it & 1;
#pragma unroll
        for (int kk = 0; kk < 16; kk += 8) {
            uint32_t a0 = f2tf(__uint_as_float(As[st * AS_SZ + (wm + gid) * AS_STR + kk + t4]));
            uint32_t a1 = f2tf(__uint_as_float(As[st * AS_SZ + (wm + gid + 8) * AS_STR + kk + t4]));
            uint32_t a2 = f2tf(__uint_as_float(As[st * AS_SZ + (wm + gid) * AS_STR + kk + t4 + 4]));
            uint32_t a3 = f2tf(__uint_as_float(As[st * AS_SZ + (wm + gid + 8) * AS_STR + kk + t4 + 4]));
#pragma unroll
            for (int nt = 0; nt < 8; nt++) {
                uint32_t b0 = Bs[st * BS_SZ + (kk + t4) * BS_STR + wn + nt * 8 + gid];
                uint32_t b1 = Bs[st * BS_SZ + (kk + t4 + 4) * BS_STR + wn + nt * 8 + gid];
                mma8(acc[nt], a0, a1, a2, a3, b0, b1);
            }
        }
        __syncthreads();
        if (it + 2 < NIT) issue(it + 2);
        cp_commit();
    }

    float* __restrict__ P = g_msgp[d * 4 + sp];
#pragma unroll
    for (int nt = 0; nt < 8; nt++)
#pragma unroll
        for (int r = 0; r < 2; r++)
#pragma unroll
            for (int e = 0; e < 2; e++) {
                int m = m0 + wm + gid + r * 8;
                int c = wn + nt * 8 + t4 * 2 + e;
                P[(size_t)m * HH + c] = acc[nt][r * 2 + e];
            }
    __threadfence();
    __syncthreads();
    if (t == 0) {
        unsigned old = atomicAdd(&g_cnt[d][mb], 1u);
        *s_last = ((old & 3u) == 3u);
    }
    __syncthreads();
    if (*s_last) {
        __threadfence();
        const float* __restrict__ P0 = g_msgp[d * 4 + 0];
        const float* __restrict__ P1 = g_msgp[d * 4 + 1];
        const float* __restrict__ P2 = g_msgp[d * 4 + 2];
        const float* __restrict__ P3 = g_msgp[d * 4 + 3];
        uint32_t* __restrict__ O = g_msg_tf[d];
        for (int i = t * 4; i < 64 * HH; i += 1024) {
            size_t off = (size_t)(m0 + (i >> 7)) * HH + (i & 127);
            float4 v0 = *(const float4*)&P0[off];
            float4 v1 = *(const float4*)&P1[off];
            float4 v2 = *(const float4*)&P2[off];
            float4 v3 = *(const float4*)&P3[off];
            uint4 o;
            o.x = f2tf((v0.x + v1.x) + (v2.x + v3.x));
            o.y = f2tf((v0.y + v1.y) + (v2.y + v3.y));
            o.z = f2tf((v0.z + v1.z) + (v2.z + v3.z));
            o.w = f2tf((v0.w + v1.w) + (v2.w + v3.w));
            *(uint4*)&O[off] = o;
        }
    }
}

// ============================================================
// layer tile: z = [msg|h|xs_t] @ Wcat (K=384) + fused LSTM cell.
// block tile 64x128 (gate-interleaved cols), warp 16x64.
// ============================================================
__device__ __forceinline__ void layer_tile(const float* __restrict__ fb,
                                           const float* __restrict__ bb,
                                           int s, int layer, int writeF,
                                           int bh, int mb, int d,
                                           uint32_t* As, uint32_t* Bs) {
    int tt = d ? (TT - 1 - s) : s;
    const uint32_t* __restrict__ Am = g_msg_tf[d];
    const uint32_t* __restrict__ Ah = layer ? g_H1tf[d] : g_H0tf[d];
    const uint32_t* __restrict__ Ax = g_xs_tf + (size_t)tt * NN * HH;
    const uint32_t* __restrict__ Wg = g_W[d];
    const float* __restrict__ bias = d ? bb : fb;
    const float* __restrict__ Cin  = layer ? g_C1[d] : g_C0[d];
    float* __restrict__ Cout = layer ? g_C0[d] : g_C1[d];
    uint32_t* __restrict__ HoutTf = layer ? g_H0tf[d] : g_H1tf[d];
    float* __restrict__ HoutF = g_H0f[d];

    int t = threadIdx.x, w = t >> 5, lane = t & 31, gid = lane >> 2, t4 = lane & 3;
    int wm = (w >> 1) * 16, wn = (w & 1) * 64;
    int m0 = mb * 64;
    float acc[8][4] = {};
    int arow = t >> 2, apart = (t & 3) * 4;
    const int NIT = 24;

    auto issue = [&](int it) {
        int st = it & 1;
        int k0 = it * 16;
        const uint32_t* Abase; int ko;
        if (k0 < 128)      { Abase = Am; ko = k0; }
        else if (k0 < 256) { Abase = Ah; ko = k0 - 128; }
        else               { Abase = Ax; ko = k0 - 256; }
        cpa16(s2u(&As[st * AS_SZ + arow * AS_STR + apart]),
              &Abase[(size_t)(m0 + arow) * HH + ko + apart]);
#pragma unroll
        for (int j2 = 0; j2 < 2; j2++) {
            int idx = t + 256 * j2;
            int br = idx >> 5, pc = (idx & 31) * 4;
            cpa16(s2u(&Bs[st * BS_SZ + br * BS_STR + pc]),
                  &Wg[(size_t)(k0 + br) * 512 + bh * 128 + pc]);
        }
    };

    issue(0); cp_commit();
    issue(1); cp_commit();

    for (int it = 0; it < NIT; it++) {
        cp_wait1();
        __syncthreads();
        int st = it & 1;
#pragma unroll
        for (int kk = 0; kk < 16; kk += 8) {
            uint32_t a0 = As[st * AS_SZ + (wm + gid) * AS_STR + kk + t4];
            uint32_t a1 = As[st * AS_SZ + (wm + gid + 8) * AS_STR + kk + t4];
            uint32_t a2 = As[st * AS_SZ + (wm + gid) * AS_STR + kk + t4 + 4];
            uint32_t a3 = As[st * AS_SZ + (wm + gid + 8) * AS_STR + kk + t4 + 4];
#pragma unroll
            for (int nt = 0; nt < 8; nt++) {
                uint32_t b0 = Bs[st * BS_SZ + (kk + t4) * BS_STR + wn + nt * 8 + gid];
                uint32_t b1 = Bs[st * BS_SZ + (kk + t4 + 4) * BS_STR + wn + nt * 8 + gid];
                mma8(acc[nt], a0, a1, a2, a3, b0, b1);
            }
        }
        __syncthreads();
        if (it + 2 < NIT) issue(it + 2);
        cp_commit();
    }

#pragma unroll
    for (int r = 0; r < 2; r++) {
        int m = m0 + wm + gid + r * 8;
#pragma unroll
        for (int jg = 0; jg < 2; jg++) {
#pragma unroll
            for (int e = 0; e < 2; e++) {
                int h = bh * 32 + (w & 1) * 16 + jg * 8 + t4 * 2 + e;
                int ci = r * 2 + e;
                float zi = acc[jg * 4 + 0][ci] + bias[0 * HH + h];
                float zf = acc[jg * 4 + 1][ci] + bias[1 * HH + h];
                float zo = acc[jg * 4 + 2][ci] + bias[2 * HH + h];
                float zg = acc[jg * 4 + 3][ci] + bias[3 * HH + h];
                float c_old = Cin[(size_t)m * HH + h];
                float c2 = sigm(zf) * c_old + sigm(zi) * tanhf(zg);
                float h2 = sigm(zo) * tanhf(c2);
                Cout[(size_t)m * HH + h] = c2;
                HoutTf[(size_t)m * HH + h] = f2tf(h2);
                if (writeF) HoutF[(size_t)m * HH + h] = h2;
            }
        }
    }
}

// ============================================================
// k_steps: persistent kernel — the whole 32-step recurrence.
// 128 blocks x 256 thr; 3 phases/step with grid barriers.
// ============================================================
__global__ void __launch_bounds__(256)
k_steps(const float* __restrict__ adjs,
        const float* __restrict__ fb, const float* __restrict__ bb) {
    __shared__ uint32_t As[2 * AS_SZ];
    __shared__ uint32_t Bs[2 * BS_SZ];
    __shared__ int s_last;

    int b = blockIdx.x;
    int q0 = b & 3;            // split (msg) / h-block (layer)
    int mb = (b >> 2) & 15;
    int d  = b >> 6;
    unsigned target = 0;

    for (int s = 0; s < TT; s++) {
        msg_tile(adjs, s, q0, mb, d, As, Bs, &s_last);
        target += NB; grid_bar(target);
        layer_tile(fb, bb, s, 0, 0, q0, mb, d, As, Bs);
        target += NB; grid_bar(target);
        layer_tile(fb, bb, s, 1, (s == TT - 1), q0, mb, d, As, Bs);
        if (s != TT - 1) { target += NB; grid_bar(target); }
    }
}

// ============================================================
// final: y[n] = [h_f | h_b][n] . v + v[256]
// ============================================================
__global__ void k_final(float* __restrict__ out) {
    int warp = threadIdx.x >> 5;
    int lane = threadIdx.x & 31;
    int n = blockIdx.x * 8 + warp;
    float s = 0.0f;
#pragma unroll
    for (int j = lane; j < 2 * HH; j += 32) {
        float hv = (j < HH) ? g_H0f[0][(size_t)n * HH + j]
                            : g_H0f[1][(size_t)n * HH + (j - HH)];
        s += hv * g_v[j];
    }
#pragma unroll
    for (int o = 16; o > 0; o >>= 1) s += __shfl_down_sync(0xffffffffu, s, o);
    if (lane == 0) out[n] = s + g_v[2 * HH];
}

// ============================================================
extern "C" void kernel_launch(void* const* d_in, const int* in_sizes, int n_in,
                              void* d_out, int out_size) {
    const float* x     = (const float*)d_in[0];
    const float* adjs  = (const float*)d_in[1];
    const float* Winw  = (const float*)d_in[3];
    const float* Winb  = (const float*)d_in[4];
    const float* fWx   = (const float*)d_in[5];
    const float* fWh   = (const float*)d_in[6];
    const float* fWn   = (const float*)d_in[7];
    const float* fb    = (const float*)d_in[8];
    const float* bWx   = (const float*)d_in[9];
    const float* bWh   = (const float*)d_in[10];
    const float* bWn   = (const float*)d_in[11];
    const float* bb    = (const float*)d_in[12];
    const float* fc0w  = (const float*)d_in[13];
    const float* fc0b  = (const float*)d_in[14];
    const float* woutw = (const float*)d_in[15];
    const float* woutb = (const float*)d_in[16];
    float* out = (float*)d_out;

    k_xs<<<dim3(2, 512), 256>>>(x, Winw, Winb);
    k_prep<<<1, 288>>>(fc0w, fc0b, woutw, woutb);
    k_wprep<<<(2 * 384 * 512 + 255) / 256, 256>>>(fWn, fWh, fWx, bWn, bWh, bWx);
    k_init<<<(2 * NN * HH) / 256, 256>>>();

    k_steps<<<NB, 256>>>(adjs, fb, bb);

    k_final<<<NN / 8, 256>>>(out);
}

// round 8
// speedup vs baseline: 3.5096x; 1.0158x over previous
#include <cuda_runtime.h>
#include <math.h>
#include <stdint.h>

#define TT 32
#define NN 1024
#define FF 64
#define HH 128
#define H4 512
#define NB 128          // persistent grid size (<=148 SMs, all co-resident)

// ---- scratch (static __device__ arrays; no runtime allocation) ----
__device__ float    g_xs[TT * NN * HH];        // fp32 xs
__device__ uint32_t g_xs_tf[TT * NN * HH];     // tf32 xs
__device__ float    g_msgp[8][NN * HH];        // split-K=4 partials per dir
__device__ uint32_t g_msg_tf[2][NN * HH];      // summed msg, tf32
__device__ float    g_H0f[2][NN * HH];         // final h_time fp32 (k_final)
__device__ uint32_t g_H0tf[2][NN * HH];        // h_time tf32
__device__ uint32_t g_H1tf[2][NN * HH];        // layer-1 h tf32
__device__ float    g_C0[2][NN * HH];
__device__ float    g_C1[2][NN * HH];
__device__ uint32_t g_W[2][384 * 512];         // pre-gathered tf32 [Wn;Wh;Wx]
__device__ float    g_v[2 * HH + 1];
// sync words, all monotone within one launch, reset by k_init each replay:
//  [0]        : global barrier arrivals
//  [16+g]     : split-K completion count, group g = d*16+mb
//  [48+g]     : msg reduction done count (1/step)
//  [80+g]     : layer0 done count (4/step)
__device__ unsigned g_sync[128];

__device__ __forceinline__ float sigm(float x) { return 1.0f / (1.0f + expf(-x)); }

__device__ __forceinline__ uint32_t f2tf(float f) {
    uint32_t u;
    asm("cvt.rna.tf32.f32 %0, %1;" : "=r"(u) : "f"(f));
    return u;
}

__device__ __forceinline__ void mma8(float* c, uint32_t a0, uint32_t a1, uint32_t a2,
                                     uint32_t a3, uint32_t b0, uint32_t b1) {
    asm volatile(
        "mma.sync.aligned.m16n8k8.row.col.f32.tf32.tf32.f32 "
        "{%0,%1,%2,%3},{%4,%5,%6,%7},{%8,%9},{%0,%1,%2,%3};"
        : "+f"(c[0]), "+f"(c[1]), "+f"(c[2]), "+f"(c[3])
        : "r"(a0), "r"(a1), "r"(a2), "r"(a3), "r"(b0), "r"(b1));
}

__device__ __forceinline__ void cpa16(uint32_t dst, const void* src) {
    asm volatile("cp.async.cg.shared.global [%0], [%1], 16;" :: "r"(dst), "l"(src));
}
__device__ __forceinline__ void cp_commit() { asm volatile("cp.async.commit_group;"); }
__device__ __forceinline__ void cp_wait2()  { asm volatile("cp.async.wait_group 2;" ::: "memory"); }
__device__ __forceinline__ uint32_t s2u(const void* p) {
    return (uint32_t)__cvta_generic_to_shared(p);
}
__device__ __forceinline__ unsigned ld_acq(const unsigned* p) {
    unsigned v;
    asm volatile("ld.acquire.gpu.global.u32 %0, [%1];" : "=r"(v) : "l"(p));
    return v;
}

// grid-wide barrier (1x per step): monotone counter.
__device__ __forceinline__ void grid_bar(unsigned target) {
    __threadfence();
    __syncthreads();
    if (threadIdx.x == 0) {
        atomicAdd(&g_sync[0], 1u);
        while (ld_acq(&g_sync[0]) < target) __nanosleep(32);
    }
    __syncthreads();
}

// smem strides (uint32 units), conflict-free fragment reads
#define AS_STR 20
#define BS_STR 136
#define AS_SZ (64 * AS_STR)
#define BS_SZ (16 * BS_STR)

// ============================================================
// k_xs (fp32, once): xs = x @ Win^T + b ; fp32 + tf32 copies
// ============================================================
__global__ void k_xs(const float* __restrict__ x,
                     const float* __restrict__ Ww,
                     const float* __restrict__ Wb) {
    __shared__ float As[16][68];
    __shared__ float Bs[16][64];
    int tid = threadIdx.x;
    int tx = tid & 15, ty = tid >> 4;
    int m0 = blockIdx.y * 64;
    int n0 = blockIdx.x * 64;
    float acc[4][4] = {};
    int arow = tid >> 2;
    int akq  = (tid & 3) * 4;
    int bn   = tid & 63;
    int bkq  = (tid >> 6) * 4;
    for (int k0 = 0; k0 < FF; k0 += 16) {
        float4 av = *(const float4*)&x[(size_t)(m0 + arow) * FF + k0 + akq];
        As[akq + 0][arow] = av.x; As[akq + 1][arow] = av.y;
        As[akq + 2][arow] = av.z; As[akq + 3][arow] = av.w;
        float4 bv = *(const float4*)&Ww[(size_t)(n0 + bn) * FF + k0 + bkq];
        Bs[bkq + 0][bn] = bv.x; Bs[bkq + 1][bn] = bv.y;
        Bs[bkq + 2][bn] = bv.z; Bs[bkq + 3][bn] = bv.w;
        __syncthreads();
#pragma unroll
        for (int kk = 0; kk < 16; kk++) {
            float4 b4 = *(const float4*)&Bs[kk][tx * 4];
            float a0 = As[kk][ty * 4 + 0], a1 = As[kk][ty * 4 + 1];
            float a2 = As[kk][ty * 4 + 2], a3 = As[kk][ty * 4 + 3];
            acc[0][0] += a0 * b4.x; acc[0][1] += a0 * b4.y; acc[0][2] += a0 * b4.z; acc[0][3] += a0 * b4.w;
            acc[1][0] += a1 * b4.x; acc[1][1] += a1 * b4.y; acc[1][2] += a1 * b4.z; acc[1][3] += a1 * b4.w;
            acc[2][0] += a2 * b4.x; acc[2][1] += a2 * b4.y; acc[2][2] += a2 * b4.z; acc[2][3] += a2 * b4.w;
            acc[3][0] += a3 * b4.x; acc[3][1] += a3 * b4.y; acc[3][2] += a3 * b4.z; acc[3][3] += a3 * b4.w;
        }
        __syncthreads();
    }
#pragma unroll
    for (int r = 0; r < 4; r++) {
        int m = m0 + ty * 4 + r;
#pragma unroll
        for (int c = 0; c < 4; c++) {
            int n = n0 + tx * 4 + c;
            float v = acc[r][c] + Wb[n];
            g_xs[(size_t)m * HH + n] = v;
            g_xs_tf[(size_t)m * HH + n] = f2tf(v);
        }
    }
}

// ============================================================
// k_wprep (once): gate-gathered tf32 weight cat [Wn;Wh;Wx] per dir
// ============================================================
__global__ void k_wprep(const float* __restrict__ fWn, const float* __restrict__ fWh,
                        const float* __restrict__ fWx,
                        const float* __restrict__ bWn, const float* __restrict__ bWh,
                        const float* __restrict__ bWx) {
    int i = blockIdx.x * blockDim.x + threadIdx.x;
    if (i >= 2 * 384 * 512) return;
    int d = i / (384 * 512);
    int rem = i - d * (384 * 512);
    int k = rem >> 9;
    int c = rem & 511;
    int b = c >> 7, cl = c & 127, nt = cl >> 3, wi = cl & 7;
    int g = nt & 3, j = ((nt >> 2) << 3) + wi;
    int srccol = g * HH + b * 32 + j;
    const float* W; int kr;
    if (k < 128)      { W = d ? bWn : fWn; kr = k; }
    else if (k < 256) { W = d ? bWh : fWh; kr = k - 128; }
    else              { W = d ? bWx : fWx; kr = k - 256; }
    g_W[d][rem] = f2tf(W[(size_t)kr * H4 + srccol]);
}

// ============================================================
// k_init: H0 = C0 = first frame; reset all sync words
// ============================================================
__global__ void k_init() {
    int i = blockIdx.x * blockDim.x + threadIdx.x;
    if (i < 128) g_sync[i] = 0u;
    int d = i / (NN * HH);
    int r = i - d * (NN * HH);
    int t0 = d ? (TT - 1) : 0;
    float v = g_xs[(size_t)t0 * NN * HH + r];
    g_H0tf[d][r] = f2tf(v);
    g_C0[d][r] = v;
}

// ============================================================
// k_prep: v[j] = wout_w . fc0_w[:,j] ;  v[256] = fused scalar bias
// ============================================================
__global__ void k_prep(const float* __restrict__ fc0w,
                       const float* __restrict__ fc0b,
                       const float* __restrict__ woutw,
                       const float* __restrict__ woutb) {
    int j = threadIdx.x;
    if (j < 2 * HH) {
        float s = 0.0f;
        for (int k = 0; k < HH; k++) s += woutw[k] * fc0w[(size_t)k * (2 * HH) + j];
        g_v[j] = s;
    } else if (j == 2 * HH) {
        float s = woutb[0];
        for (int k = 0; k < HH; k++) s += woutw[k] * fc0b[k];
        g_v[2 * HH] = s;
    }
}

// ============================================================
// msg tile: split sp of adj_t @ H0tf -> g_msgp; last block of group
// (d,mb) reduces 4 partials -> g_msg_tf and signals msgdone.
// Non-reducers spin on msgdone (group-local sync, 4 blocks).
// 3-stage cp.async pipeline. block tile 64x128, warp 16x64.
// ============================================================
__device__ __forceinline__ void msg_tile(const float* __restrict__ adjs, int s,
                                         int sp, int mb, int d,
                                         uint32_t* As, uint32_t* Bs, int* s_flag) {
    int tt = d ? (TT - 1 - s) : s;
    const float* __restrict__ A = adjs + (size_t)tt * NN * NN;
    const uint32_t* __restrict__ B = g_H0tf[d];
    int grp = d * 16 + mb;

    int t = threadIdx.x, w = t >> 5, lane = t & 31, gid = lane >> 2, t4 = lane & 3;
    int wm = (w >> 1) * 16, wn = (w & 1) * 64;
    int m0 = mb * 64;
    int kbeg = sp * 256;
    float acc[8][4] = {};
    int arow = t >> 2, apart = (t & 3) * 4;
    const int NIT = 16;

    auto issue = [&](int it) {
        int st = it % 3;
        int k0 = kbeg + it * 16;
        cpa16(s2u(&As[st * AS_SZ + arow * AS_STR + apart]),
              &A[(size_t)(m0 + arow) * NN + k0 + apart]);
#pragma unroll
        for (int j2 = 0; j2 < 2; j2++) {
            int idx = t + 256 * j2;
            int br = idx >> 5, pc = (idx & 31) * 4;
            cpa16(s2u(&Bs[st * BS_SZ + br * BS_STR + pc]),
                  &B[(size_t)(k0 + br) * HH + pc]);
        }
    };

    issue(0); cp_commit();
    issue(1); cp_commit();
    issue(2); cp_commit();

    for (int it = 0; it < NIT; it++) {
        cp_wait2();
        __syncthreads();
        int st = it % 3;
#pragma unroll
        for (int kk = 0; kk < 16; kk += 8) {
            uint32_t a0 = f2tf(__uint_as_float(As[st * AS_SZ + (wm + gid) * AS_STR + kk + t4]));
            uint32_t a1 = f2tf(__uint_as_float(As[st * AS_SZ + (wm + gid + 8) * AS_STR + kk + t4]));
            uint32_t a2 = f2tf(__uint_as_float(As[st * AS_SZ + (wm + gid) * AS_STR + kk + t4 + 4]));
            uint32_t a3 = f2tf(__uint_as_float(As[st * AS_SZ + (wm + gid + 8) * AS_STR + kk + t4 + 4]));
#pragma unroll
            for (int nt = 0; nt < 8; nt++) {
                uint32_t b0 = Bs[st * BS_SZ + (kk + t4) * BS_STR + wn + nt * 8 + gid];
                uint32_t b1 = Bs[st * BS_SZ + (kk + t4 + 4) * BS_STR + wn + nt * 8 + gid];
                mma8(acc[nt], a0, a1, a2, a3, b0, b1);
            }
        }
        __syncthreads();
        if (it + 3 < NIT) issue(it + 3);
        cp_commit();
    }

    float* __restrict__ P = g_msgp[d * 4 + sp];
#pragma unroll
    for (int nt = 0; nt < 8; nt++)
#pragma unroll
        for (int r = 0; r < 2; r++)
#pragma unroll
            for (int e = 0; e < 2; e++) {
                int m = m0 + wm + gid + r * 8;
                int c = wn + nt * 8 + t4 * 2 + e;
                P[(size_t)m * HH + c] = acc[nt][r * 2 + e];
            }
    __threadfence();
    __syncthreads();
    if (t == 0) {
        unsigned old = atomicAdd(&g_sync[16 + grp], 1u);
        *s_flag = ((old & 3u) == 3u);
    }
    __syncthreads();
    if (*s_flag) {
        // reduce 4 partials -> tf32 msg; then signal group
        __threadfence();
        const float* __restrict__ P0 = g_msgp[d * 4 + 0];
        const float* __restrict__ P1 = g_msgp[d * 4 + 1];
        const float* __restrict__ P2 = g_msgp[d * 4 + 2];
        const float* __restrict__ P3 = g_msgp[d * 4 + 3];
        uint32_t* __restrict__ O = g_msg_tf[d];
        for (int i = t * 4; i < 64 * HH; i += 1024) {
            size_t off = (size_t)(m0 + (i >> 7)) * HH + (i & 127);
            float4 v0 = *(const float4*)&P0[off];
            float4 v1 = *(const float4*)&P1[off];
            float4 v2 = *(const float4*)&P2[off];
            float4 v3 = *(const float4*)&P3[off];
            uint4 o;
            o.x = f2tf((v0.x + v1.x) + (v2.x + v3.x));
            o.y = f2tf((v0.y + v1.y) + (v2.y + v3.y));
            o.z = f2tf((v0.z + v1.z) + (v2.z + v3.z));
            o.w = f2tf((v0.w + v1.w) + (v2.w + v3.w));
            *(uint4*)&O[off] = o;
        }
        __threadfence();
        __syncthreads();
        if (t == 0) atomicAdd(&g_sync[48 + grp], 1u);
        // reducer proceeds immediately (it owns the data)
    } else {
        if (t == 0)
            while (ld_acq(&g_sync[48 + grp]) < (unsigned)(s + 1)) __nanosleep(32);
        __syncthreads();
    }
}

// ============================================================
// layer tile: z = [msg|h|xs_t] @ Wcat (K=384) + fused LSTM cell.
// block tile 64x128 (gate-interleaved cols), warp 16x64.
// ============================================================
__device__ __forceinline__ void layer_tile(const float* __restrict__ fb,
                                           const float* __restrict__ bb,
                                           int s, int layer, int writeF,
                                           int bh, int mb, int d,
                                           uint32_t* As, uint32_t* Bs) {
    int tt = d ? (TT - 1 - s) : s;
    const uint32_t* __restrict__ Am = g_msg_tf[d];
    const uint32_t* __restrict__ Ah = layer ? g_H1tf[d] : g_H0tf[d];
    const uint32_t* __restrict__ Ax = g_xs_tf + (size_t)tt * NN * HH;
    const uint32_t* __restrict__ Wg = g_W[d];
    const float* __restrict__ bias = d ? bb : fb;
    const float* __restrict__ Cin  = layer ? g_C1[d] : g_C0[d];
    float* __restrict__ Cout = layer ? g_C0[d] : g_C1[d];
    uint32_t* __restrict__ HoutTf = layer ? g_H0tf[d] : g_H1tf[d];
    float* __restrict__ HoutF = g_H0f[d];

    int t = threadIdx.x, w = t >> 5, lane = t & 31, gid = lane >> 2, t4 = lane & 3;
    int wm = (w >> 1) * 16, wn = (w & 1) * 64;
    int m0 = mb * 64;
    float acc[8][4] = {};
    int arow = t >> 2, apart = (t & 3) * 4;
    const int NIT = 24;

    auto issue = [&](int it) {
        int st = it % 3;
        int k0 = it * 16;
        const uint32_t* Abase; int ko;
        if (k0 < 128)      { Abase = Am; ko = k0; }
        else if (k0 < 256) { Abase = Ah; ko = k0 - 128; }
        else               { Abase = Ax; ko = k0 - 256; }
        cpa16(s2u(&As[st * AS_SZ + arow * AS_STR + apart]),
              &Abase[(size_t)(m0 + arow) * HH + ko + apart]);
#pragma unroll
        for (int j2 = 0; j2 < 2; j2++) {
            int idx = t + 256 * j2;
            int br = idx >> 5, pc = (idx & 31) * 4;
            cpa16(s2u(&Bs[st * BS_SZ + br * BS_STR + pc]),
                  &Wg[(size_t)(k0 + br) * 512 + bh * 128 + pc]);
        }
    };

    issue(0); cp_commit();
    issue(1); cp_commit();
    issue(2); cp_commit();

    for (int it = 0; it < NIT; it++) {
        cp_wait2();
        __syncthreads();
        int st = it % 3;
#pragma unroll
        for (int kk = 0; kk < 16; kk += 8) {
            uint32_t a0 = As[st * AS_SZ + (wm + gid) * AS_STR + kk + t4];
            uint32_t a1 = As[st * AS_SZ + (wm + gid + 8) * AS_STR + kk + t4];
            uint32_t a2 = As[st * AS_SZ + (wm + gid) * AS_STR + kk + t4 + 4];
            uint32_t a3 = As[st * AS_SZ + (wm + gid + 8) * AS_STR + kk + t4 + 4];
#pragma unroll
            for (int nt = 0; nt < 8; nt++) {
                uint32_t b0 = Bs[st * BS_SZ + (kk + t4) * BS_STR + wn + nt * 8 + gid];
                uint32_t b1 = Bs[st * BS_SZ + (kk + t4 + 4) * BS_STR + wn + nt * 8 + gid];
                mma8(acc[nt], a0, a1, a2, a3, b0, b1);
            }
        }
        __syncthreads();
        if (it + 3 < NIT) issue(it + 3);
        cp_commit();
    }

#pragma unroll
    for (int r = 0; r < 2; r++) {
        int m = m0 + wm + gid + r * 8;
#pragma unroll
        for (int jg = 0; jg < 2; jg++) {
#pragma unroll
            for (int e = 0; e < 2; e++) {
                int h = bh * 32 + (w & 1) * 16 + jg * 8 + t4 * 2 + e;
                int ci = r * 2 + e;
                float zi = acc[jg * 4 + 0][ci] + bias[0 * HH + h];
                float zf = acc[jg * 4 + 1][ci] + bias[1 * HH + h];
                float zo = acc[jg * 4 + 2][ci] + bias[2 * HH + h];
                float zg = acc[jg * 4 + 3][ci] + bias[3 * HH + h];
                float c_old = Cin[(size_t)m * HH + h];
                float c2 = sigm(zf) * c_old + sigm(zi) * tanhf(zg);
                float h2 = sigm(zo) * tanhf(c2);
                Cout[(size_t)m * HH + h] = c2;
                HoutTf[(size_t)m * HH + h] = f2tf(h2);
                if (writeF) HoutF[(size_t)m * HH + h] = h2;
            }
        }
    }
}

// ============================================================
// k_steps: persistent kernel — whole 32-step recurrence.
// Per step: msg -> [group sync] -> layer0 -> [group sync: 4 blocks]
//           -> layer1 -> [GLOBAL barrier] (except last step).
// ============================================================
__global__ void __launch_bounds__(256)
k_steps(const float* __restrict__ adjs,
        const float* __restrict__ fb, const float* __restrict__ bb) {
    __shared__ uint32_t As[3 * AS_SZ];
    __shared__ uint32_t Bs[3 * BS_SZ];
    __shared__ int s_flag;

    int b = blockIdx.x;
    int q0 = b & 3;            // split (msg) / h-block (layer)
    int mb = (b >> 2) & 15;
    int d  = b >> 6;
    int grp = d * 16 + mb;
    int t = threadIdx.x;

    for (int s = 0; s < TT; s++) {
        // phase 1: msg GEMM + group-local reduction sync (inside msg_tile)
        msg_tile(adjs, s, q0, mb, d, As, Bs, &s_flag);

        // phase 2: layer 0, then 4-block group sync
        layer_tile(fb, bb, s, 0, 0, q0, mb, d, As, Bs);
        __threadfence();
        __syncthreads();
        if (t == 0) {
            atomicAdd(&g_sync[80 + grp], 1u);
            while (ld_acq(&g_sync[80 + grp]) < 4u * (unsigned)(s + 1)) __nanosleep(32);
        }
        __syncthreads();

        // phase 3: layer 1, then global barrier (H0 feeds all msg tiles)
        layer_tile(fb, bb, s, 1, (s == TT - 1), q0, mb, d, As, Bs);
        if (s != TT - 1) grid_bar((unsigned)NB * (unsigned)(s + 1));
    }
}

// ============================================================
// final: y[n] = [h_f | h_b][n] . v + v[256]
// ============================================================
__global__ void k_final(float* __restrict__ out) {
    int warp = threadIdx.x >> 5;
    int lane = threadIdx.x & 31;
    int n = blockIdx.x * 8 + warp;
    float s = 0.0f;
#pragma unroll
    for (int j = lane; j < 2 * HH; j += 32) {
        float hv = (j < HH) ? g_H0f[0][(size_t)n * HH + j]
                            : g_H0f[1][(size_t)n * HH + (j - HH)];
        s += hv * g_v[j];
    }
#pragma unroll
    for (int o = 16; o > 0; o >>= 1) s += __shfl_down_sync(0xffffffffu, s, o);
    if (lane == 0) out[n] = s + g_v[2 * HH];
}

// ============================================================
extern "C" void kernel_launch(void* const* d_in, const int* in_sizes, int n_in,
                              void* d_out, int out_size) {
    const float* x     = (const float*)d_in[0];
    const float* adjs  = (const float*)d_in[1];
    const float* Winw  = (const float*)d_in[3];
    const float* Winb  = (const float*)d_in[4];
    const float* fWx   = (const float*)d_in[5];
    const float* fWh   = (const float*)d_in[6];
    const float* fWn   = (const float*)d_in[7];
    const float* fb    = (const float*)d_in[8];
    const float* bWx   = (const float*)d_in[9];
    const float* bWh   = (const float*)d_in[10];
    const float* bWn   = (const float*)d_in[11];
    const float* bb    = (const float*)d_in[12];
    const float* fc0w  = (const float*)d_in[13];
    const float* fc0b  = (const float*)d_in[14];
    const float* woutw = (const float*)d_in[15];
    const float* woutb = (const float*)d_in[16];
    float* out = (float*)d_out;

    k_xs<<<dim3(2, 512), 256>>>(x, Winw, Winb);
    k_prep<<<1, 288>>>(fc0w, fc0b, woutw, woutb);
    k_wprep<<<(2 * 384 * 512 + 255) / 256, 256>>>(fWn, fWh, fWx, bWn, bWh, bWx);
    k_init<<<(2 * NN * HH) / 256, 256>>>();

    k_steps<<<NB, 256>>>(adjs, fb, bb);

    k_final<<<NN / 8, 256>>>(out);
}

// round 11
// speedup vs baseline: 3.6745x; 1.0470x over previous
#include <cuda_runtime.h>
#include <math.h>
#include <stdint.h>

#define TT 32
#define NN 1024
#define FF 64
#define HH 128
#define H4 512
#define NB 128          // persistent grid size (<=148 SMs, all co-resident)

// ---- scratch (static __device__ arrays; no runtime allocation) ----
__device__ float    g_xs[TT * NN * HH];        // fp32 xs
__device__ uint32_t g_xs_tf[TT * NN * HH];     // tf32 xs
__device__ float    g_xbg[2][TT * NN * H4];    // 128 MB: xs@Wx + b, gate-gathered cols
__device__ float    g_msgp[8][NN * HH];        // split-K=4 partials per dir
__device__ uint32_t g_msg_tf[2][NN * HH];      // summed msg, tf32
__device__ float    g_H0f[2][NN * HH];         // final h_time fp32 (k_final)
__device__ uint32_t g_H0tf[2][NN * HH];        // h_time tf32
__device__ uint32_t g_H1tf[2][NN * HH];        // layer-1 h tf32
__device__ float    g_C0[2][NN * HH];
__device__ float    g_C1[2][NN * HH];
__device__ uint32_t g_W[2][384 * 512];         // pre-gathered tf32 [Wn;Wh;Wx]
__device__ float    g_v[2 * HH + 1];
// sync words (monotone per launch, reset by k_init):
//  [0] global barrier; [16+g] split-K done; [48+g] msg reduced; [80+g] layer0 done
__device__ unsigned g_sync[128];

__device__ __forceinline__ float sigm(float x) { return 1.0f / (1.0f + expf(-x)); }

__device__ __forceinline__ uint32_t f2tf(float f) {
    uint32_t u;
    asm("cvt.rna.tf32.f32 %0, %1;" : "=r"(u) : "f"(f));
    return u;
}

__device__ __forceinline__ void mma8(float* c, uint32_t a0, uint32_t a1, uint32_t a2,
                                     uint32_t a3, uint32_t b0, uint32_t b1) {
    asm volatile(
        "mma.sync.aligned.m16n8k8.row.col.f32.tf32.tf32.f32 "
        "{%0,%1,%2,%3},{%4,%5,%6,%7},{%8,%9},{%0,%1,%2,%3};"
        : "+f"(c[0]), "+f"(c[1]), "+f"(c[2]), "+f"(c[3])
        : "r"(a0), "r"(a1), "r"(a2), "r"(a3), "r"(b0), "r"(b1));
}

__device__ __forceinline__ void cpa16(uint32_t dst, const void* src) {
    asm volatile("cp.async.cg.shared.global [%0], [%1], 16;" :: "r"(dst), "l"(src));
}
__device__ __forceinline__ void cp_commit() { asm volatile("cp.async.commit_group;"); }
__device__ __forceinline__ void cp_wait1()  { asm volatile("cp.async.wait_group 1;" ::: "memory"); }
__device__ __forceinline__ uint32_t s2u(const void* p) {
    return (uint32_t)__cvta_generic_to_shared(p);
}
__device__ __forceinline__ unsigned ld_acq(const unsigned* p) {
    unsigned v;
    asm volatile("ld.acquire.gpu.global.u32 %0, [%1];" : "=r"(v) : "l"(p));
    return v;
}

__device__ __forceinline__ void grid_bar(unsigned target) {
    __threadfence();
    __syncthreads();
    if (threadIdx.x == 0) {
        atomicAdd(&g_sync[0], 1u);
        while (ld_acq(&g_sync[0]) < target) __nanosleep(32);
    }
    __syncthreads();
}

// smem strides (uint32 units), conflict-free fragment reads
#define AS_STR 20
#define BS_STR 136
#define AS_SZ (64 * AS_STR)      // 1280
#define BS_SZ (16 * BS_STR)      // 2176
// dynamic smem layout of k_steps (u32 units):
#define W_OFF  0                 // 256*136 = 34816 : resident gathered weights
#define A_OFF  34816             // 3 * AS_SZ = 3840
#define MB_OFF 38656             // 3 * BS_SZ = 6528
#define SMEM_U32 45184
#define SMEM_BYTES (SMEM_U32 * 4)

// ============================================================
// k_xs (fp32, once): xs = x @ Win^T + b ; fp32 + tf32 copies
// ============================================================
__global__ void k_xs(const float* __restrict__ x,
                     const float* __restrict__ Ww,
                     const float* __restrict__ Wb) {
    __shared__ float As[16][68];
    __shared__ float Bs[16][64];
    int tid = threadIdx.x;
    int tx = tid & 15, ty = tid >> 4;
    int m0 = blockIdx.y * 64;
    int n0 = blockIdx.x * 64;
    float acc[4][4] = {};
    int arow = tid >> 2;
    int akq  = (tid & 3) * 4;
    int bn   = tid & 63;
    int bkq  = (tid >> 6) * 4;
    for (int k0 = 0; k0 < FF; k0 += 16) {
        float4 av = *(const float4*)&x[(size_t)(m0 + arow) * FF + k0 + akq];
        As[akq + 0][arow] = av.x; As[akq + 1][arow] = av.y;
        As[akq + 2][arow] = av.z; As[akq + 3][arow] = av.w;
        float4 bv = *(const float4*)&Ww[(size_t)(n0 + bn) * FF + k0 + bkq];
        Bs[bkq + 0][bn] = bv.x; Bs[bkq + 1][bn] = bv.y;
        Bs[bkq + 2][bn] = bv.z; Bs[bkq + 3][bn] = bv.w;
        __syncthreads();
#pragma unroll
        for (int kk = 0; kk < 16; kk++) {
            float4 b4 = *(const float4*)&Bs[kk][tx * 4];
            float a0 = As[kk][ty * 4 + 0], a1 = As[kk][ty * 4 + 1];
            float a2 = As[kk][ty * 4 + 2], a3 = As[kk][ty * 4 + 3];
            acc[0][0] += a0 * b4.x; acc[0][1] += a0 * b4.y; acc[0][2] += a0 * b4.z; acc[0][3] += a0 * b4.w;
            acc[1][0] += a1 * b4.x; acc[1][1] += a1 * b4.y; acc[1][2] += a1 * b4.z; acc[1][3] += a1 * b4.w;
            acc[2][0] += a2 * b4.x; acc[2][1] += a2 * b4.y; acc[2][2] += a2 * b4.z; acc[2][3] += a2 * b4.w;
            acc[3][0] += a3 * b4.x; acc[3][1] += a3 * b4.y; acc[3][2] += a3 * b4.z; acc[3][3] += a3 * b4.w;
        }
        __syncthreads();
    }
#pragma unroll
    for (int r = 0; r < 4; r++) {
        int m = m0 + ty * 4 + r;
#pragma unroll
        for (int c = 0; c < 4; c++) {
            int n = n0 + tx * 4 + c;
            float v = acc[r][c] + Wb[n];
            g_xs[(size_t)m * HH + n] = v;
            g_xs_tf[(size_t)m * HH + n] = f2tf(v);
        }
    }
}

// ============================================================
// k_wprep (once): gate-gathered tf32 weight cat [Wn;Wh;Wx] per dir
// ============================================================
__global__ void k_wprep(const float* __restrict__ fWn, const float* __restrict__ fWh,
                        const float* __restrict__ fWx,
                        const float* __restrict__ bWn, const float* __restrict__ bWh,
                        const float* __restrict__ bWx) {
    int i = blockIdx.x * blockDim.x + threadIdx.x;
    if (i >= 2 * 384 * 512) return;
    int d = i / (384 * 512);
    int rem = i - d * (384 * 512);
    int k = rem >> 9;
    int c = rem & 511;
    int b = c >> 7, cl = c & 127, nt = cl >> 3, wi = cl & 7;
    int g = nt & 3, j = ((nt >> 2) << 3) + wi;
    int srccol = g * HH + b * 32 + j;
    const float* W; int kr;
    if (k < 128)      { W = d ? bWn : fWn; kr = k; }
    else if (k < 256) { W = d ? bWh : fWh; kr = k - 128; }
    else              { W = d ? bWx : fWx; kr = k - 256; }
    g_W[d][rem] = f2tf(W[(size_t)kr * H4 + srccol]);
}

// ============================================================
// k_xb (tf32 TC, once): xbg[d][m][c_gathered] = xs[m,:] @ Wx_g + b_g
// C = 32768 x 512 per dir (m folds t). K=128. grid (4, 512, 2).
// ============================================================
__global__ void __launch_bounds__(256)
k_xb(const float* __restrict__ fb, const float* __restrict__ bb) {
    __shared__ uint32_t As[3][AS_SZ];
    __shared__ uint32_t Bs[3][BS_SZ];
    int bx = blockIdx.x, by = blockIdx.y, d = blockIdx.z;
    const uint32_t* __restrict__ A = g_xs_tf;
    const uint32_t* __restrict__ B = g_W[d] + 256 * 512;
    const float* __restrict__ bias = d ? bb : fb;

    int t = threadIdx.x, w = t >> 5, lane = t & 31, gid = lane >> 2, t4 = lane & 3;
    int wm = (w >> 1) * 16, wn = (w & 1) * 64;
    int m0 = by * 64;
    float acc[8][4] = {};
    int arow = t >> 2, apart = (t & 3) * 4;
    const int NIT = 8;

    auto issue = [&](int it) {
        int st = it % 3;
        int k0 = it * 16;
        cpa16(s2u(&As[st][arow * AS_STR + apart]),
              &A[(size_t)(m0 + arow) * HH + k0 + apart]);
#pragma unroll
        for (int j2 = 0; j2 < 2; j2++) {
            int idx = t + 256 * j2;
            int br = idx >> 5, pc = (idx & 31) * 4;
            cpa16(s2u(&Bs[st][br * BS_STR + pc]),
                  &B[(size_t)(k0 + br) * 512 + bx * 128 + pc]);
        }
    };
    issue(0); cp_commit();
    issue(1); cp_commit();

    for (int it = 0; it < NIT; it++) {
        cp_wait1();
        __syncthreads();
        if (it + 2 < NIT) issue(it + 2);
        cp_commit();
        int st = it % 3;
#pragma unroll
        for (int kk = 0; kk < 16; kk += 8) {
            uint32_t a0 = As[st][(wm + gid) * AS_STR + kk + t4];
            uint32_t a1 = As[st][(wm + gid + 8) * AS_STR + kk + t4];
            uint32_t a2 = As[st][(wm + gid) * AS_STR + kk + t4 + 4];
            uint32_t a3 = As[st][(wm + gid + 8) * AS_STR + kk + t4 + 4];
#pragma unroll
            for (int nt = 0; nt < 8; nt++) {
                uint32_t b0 = Bs[st][(kk + t4) * BS_STR + wn + nt * 8 + gid];
                uint32_t b1 = Bs[st][(kk + t4 + 4) * BS_STR + wn + nt * 8 + gid];
                mma8(acc[nt], a0, a1, a2, a3, b0, b1);
            }
        }
        __syncthreads();
    }

    float* __restrict__ out = g_xbg[d];
#pragma unroll
    for (int nt = 0; nt < 8; nt++)
#pragma unroll
        for (int r = 0; r < 2; r++)
#pragma unroll
            for (int e = 0; e < 2; e++) {
                int m = m0 + wm + gid + r * 8;
                int c = bx * 128 + wn + nt * 8 + t4 * 2 + e;
                // gathered -> source column (for bias)
                int b_ = c >> 7, cl = c & 127, nt2 = cl >> 3, wi = cl & 7;
                int g = nt2 & 3, j = ((nt2 >> 2) << 3) + wi;
                int src = g * HH + b_ * 32 + j;
                out[(size_t)m * H4 + c] = acc[nt][r * 2 + e] + bias[src];
            }
}

// ============================================================
// k_init: H0 = C0 = first frame; reset all sync words
// ============================================================
__global__ void k_init() {
    int i = blockIdx.x * blockDim.x + threadIdx.x;
    if (i < 128) g_sync[i] = 0u;
    int d = i / (NN * HH);
    int r = i - d * (NN * HH);
    int t0 = d ? (TT - 1) : 0;
    float v = g_xs[(size_t)t0 * NN * HH + r];
    g_H0tf[d][r] = f2tf(v);
    g_C0[d][r] = v;
}

// ============================================================
// k_prep: v[j] = wout_w . fc0_w[:,j] ;  v[256] = fused scalar bias
// ============================================================
__global__ void k_prep(const float* __restrict__ fc0w,
                       const float* __restrict__ fc0b,
                       const float* __restrict__ woutw,
                       const float* __restrict__ woutb) {
    int j = threadIdx.x;
    if (j < 2 * HH) {
        float s = 0.0f;
        for (int k = 0; k < HH; k++) s += woutw[k] * fc0w[(size_t)k * (2 * HH) + j];
        g_v[j] = s;
    } else if (j == 2 * HH) {
        float s = woutb[0];
        for (int k = 0; k < HH; k++) s += woutw[k] * fc0b[k];
        g_v[2 * HH] = s;
    }
}

// ============================================================
// msg tile: split sp of adj_t @ H0tf -> g_msgp; last block of group
// (d,mb) reduces 4 partials -> g_msg_tf; group-local sync.
// ============================================================
__device__ __forceinline__ void msg_tile(const float* __restrict__ adjs, int s,
                                         int sp, int mb, int d,
                                         uint32_t* Ast, uint32_t* Bst, int* s_flag) {
    int tt = d ? (TT - 1 - s) : s;
    const float* __restrict__ A = adjs + (size_t)tt * NN * NN;
    const uint32_t* __restrict__ B = g_H0tf[d];
    int grp = d * 16 + mb;

    int t = threadIdx.x, w = t >> 5, lane = t & 31, gid = lane >> 2, t4 = lane & 3;
    int wm = (w >> 1) * 16, wn = (w & 1) * 64;
    int m0 = mb * 64;
    int kbeg = sp * 256;
    float acc[8][4] = {};
    int arow = t >> 2, apart = (t & 3) * 4;
    const int NIT = 16;

    auto issue = [&](int it) {
        int st = it % 3;
        int k0 = kbeg + it * 16;
        cpa16(s2u(&Ast[st * AS_SZ + arow * AS_STR + apart]),
              &A[(size_t)(m0 + arow) * NN + k0 + apart]);
#pragma unroll
        for (int j2 = 0; j2 < 2; j2++) {
            int idx = t + 256 * j2;
            int br = idx >> 5, pc = (idx & 31) * 4;
            cpa16(s2u(&Bst[st * BS_SZ + br * BS_STR + pc]),
                  &B[(size_t)(k0 + br) * HH + pc]);
        }
    };
    issue(0); cp_commit();
    issue(1); cp_commit();

    for (int it = 0; it < NIT; it++) {
        cp_wait1();
        __syncthreads();
        if (it + 2 < NIT) issue(it + 2);
        cp_commit();
        int st = it % 3;
#pragma unroll
        for (int kk = 0; kk < 16; kk += 8) {
            uint32_t a0 = f2tf(__uint_as_float(Ast[st * AS_SZ + (wm + gid) * AS_STR + kk + t4]));
            uint32_t a1 = f2tf(__uint_as_float(Ast[st * AS_SZ + (wm + gid + 8) * AS_STR + kk + t4]));
            uint32_t a2 = f2tf(__uint_as_float(Ast[st * AS_SZ + (wm + gid) * AS_STR + kk + t4 + 4]));
            uint32_t a3 = f2tf(__uint_as_float(Ast[st * AS_SZ + (wm + gid + 8) * AS_STR + kk + t4 + 4]));
#pragma unroll
            for (int nt = 0; nt < 8; nt++) {
                uint32_t b0 = Bst[st * BS_SZ + (kk + t4) * BS_STR + wn + nt * 8 + gid];
                uint32_t b1 = Bst[st * BS_SZ + (kk + t4 + 4) * BS_STR + wn + nt * 8 + gid];
                mma8(acc[nt], a0, a1, a2, a3, b0, b1);
            }
        }
    }
    __syncthreads();

    float* __restrict__ P = g_msgp[d * 4 + sp];
#pragma unroll
    for (int nt = 0; nt < 8; nt++)
#pragma unroll
        for (int r = 0; r < 2; r++)
#pragma unroll
            for (int e = 0; e < 2; e++) {
                int m = m0 + wm + gid + r * 8;
                int c = wn + nt * 8 + t4 * 2 + e;
                P[(size_t)m * HH + c] = acc[nt][r * 2 + e];
            }
    __threadfence();
    __syncthreads();
    if (t == 0) {
        unsigned old = atomicAdd(&g_sync[16 + grp], 1u);
        *s_flag = ((old & 3u) == 3u);
    }
    __syncthreads();
    if (*s_flag) {
        __threadfence();
        const float* __restrict__ P0 = g_msgp[d * 4 + 0];
        const float* __restrict__ P1 = g_msgp[d * 4 + 1];
        const float* __restrict__ P2 = g_msgp[d * 4 + 2];
        const float* __restrict__ P3 = g_msgp[d * 4 + 3];
        uint32_t* __restrict__ O = g_msg_tf[d];
        for (int i = t * 4; i < 64 * HH; i += 1024) {
            size_t off = (size_t)(m0 + (i >> 7)) * HH + (i & 127);
            float4 v0 = *(const float4*)&P0[off];
            float4 v1 = *(const float4*)&P1[off];
            float4 v2 = *(const float4*)&P2[off];
            float4 v3 = *(const float4*)&P3[off];
            uint4 o;
            o.x = f2tf((v0.x + v1.x) + (v2.x + v3.x));
            o.y = f2tf((v0.y + v1.y) + (v2.y + v3.y));
            o.z = f2tf((v0.z + v1.z) + (v2.z + v3.z));
            o.w = f2tf((v0.w + v1.w) + (v2.w + v3.w));
            *(uint4*)&O[off] = o;
        }
        __threadfence();
        __syncthreads();
        if (t == 0) atomicAdd(&g_sync[48 + grp], 1u);
    } else {
        if (t == 0)
            while (ld_acq(&g_sync[48 + grp]) < (unsigned)(s + 1)) __nanosleep(32);
        __syncthreads();
    }
}

// ============================================================
// layer tile: z = [msg|h] @ Wres (K=256, weights SMEM-resident)
//             + xbg_t + fused LSTM cell.
// ============================================================
__device__ __forceinline__ void layer_tile(int s, int layer, int writeF,
                                           int bh, int mb, int d,
                                           const uint32_t* Wres, uint32_t* Ast) {
    int tt = d ? (TT - 1 - s) : s;
    const uint32_t* __restrict__ Am = g_msg_tf[d];
    const uint32_t* __restrict__ Ah = layer ? g_H1tf[d] : g_H0tf[d];
    const float* __restrict__ Cin  = layer ? g_C1[d] : g_C0[d];
    float* __restrict__ Cout = layer ? g_C0[d] : g_C1[d];
    uint32_t* __restrict__ HoutTf = layer ? g_H0tf[d] : g_H1tf[d];
    float* __restrict__ HoutF = g_H0f[d];
    const float* __restrict__ xbg = g_xbg[d] + (size_t)tt * NN * H4;

    int t = threadIdx.x, w = t >> 5, lane = t & 31, gid = lane >> 2, t4 = lane & 3;
    int wm = (w >> 1) * 16, wn = (w & 1) * 64;
    int m0 = mb * 64;
    float acc[8][4] = {};
    int arow = t >> 2, apart = (t & 3) * 4;
    const int NIT = 16;

    auto issue = [&](int it) {
        int st = it % 3;
        int k0 = it * 16;
        const uint32_t* Abase = (k0 < 128) ? Am : Ah;
        int ko = (k0 < 128) ? k0 : (k0 - 128);
        cpa16(s2u(&Ast[st * AS_SZ + arow * AS_STR + apart]),
              &Abase[(size_t)(m0 + arow) * HH + ko + apart]);
    };
    issue(0); cp_commit();
    issue(1); cp_commit();

    for (int it = 0; it < NIT; it++) {
        cp_wait1();
        __syncthreads();
        if (it + 2 < NIT) issue(it + 2);
        cp_commit();
        int st = it % 3;
        int krow = it * 16;
#pragma unroll
        for (int kk = 0; kk < 16; kk += 8) {
            uint32_t a0 = Ast[st * AS_SZ + (wm + gid) * AS_STR + kk + t4];
            uint32_t a1 = Ast[st * AS_SZ + (wm + gid + 8) * AS_STR + kk + t4];
            uint32_t a2 = Ast[st * AS_SZ + (wm + gid) * AS_STR + kk + t4 + 4];
            uint32_t a3 = Ast[st * AS_SZ + (wm + gid + 8) * AS_STR + kk + t4 + 4];
#pragma unroll
            for (int nt = 0; nt < 8; nt++) {
                uint32_t b0 = Wres[(krow + kk + t4) * BS_STR + wn + nt * 8 + gid];
                uint32_t b1 = Wres[(krow + kk + t4 + 4) * BS_STR + wn + nt * 8 + gid];
                mma8(acc[nt], a0, a1, a2, a3, b0, b1);
            }
        }
    }
    __syncthreads();

    // fused cell epilogue; xbg holds xs@Wx+b in gathered column order
#pragma unroll
    for (int r = 0; r < 2; r++) {
        int m = m0 + wm + gid + r * 8;
#pragma unroll
        for (int jg = 0; jg < 2; jg++) {
#pragma unroll
            for (int e = 0; e < 2; e++) {
                int cbase = bh * 128 + wn + jg * 32 + t4 * 2 + e;
                int ci = r * 2 + e;
                float zi = acc[jg * 4 + 0][ci] + xbg[(size_t)m * H4 + cbase + 0];
                float zf = acc[jg * 4 + 1][ci] + xbg[(size_t)m * H4 + cbase + 8];
                float zo = acc[jg * 4 + 2][ci] + xbg[(size_t)m * H4 + cbase + 16];
                float zg = acc[jg * 4 + 3][ci] + xbg[(size_t)m * H4 + cbase + 24];
                int h = bh * 32 + (w & 1) * 16 + jg * 8 + t4 * 2 + e;
                float c_old = Cin[(size_t)m * HH + h];
                float c2 = sigm(zf) * c_old + sigm(zi) * tanhf(zg);
                float h2 = sigm(zo) * tanhf(c2);
                Cout[(size_t)m * HH + h] = c2;
                HoutTf[(size_t)m * HH + h] = f2tf(h2);
                if (writeF) HoutF[(size_t)m * HH + h] = h2;
            }
        }
    }
}

// ============================================================
// k_steps: persistent kernel. Weights (256x128 slice, gathered,
// stride-136) loaded into SMEM once; A tiles streamed per phase.
// Per step: msg -> [group sync] -> layer0 -> [group sync] ->
//           layer1 -> [global barrier].
// ============================================================
__global__ void __launch_bounds__(256)
k_steps(const float* __restrict__ adjs) {
    extern __shared__ uint32_t smem[];
    uint32_t* Wres = smem + W_OFF;
    uint32_t* Ast  = smem + A_OFF;
    uint32_t* Bst  = smem + MB_OFF;
    __shared__ int s_flag;

    int b = blockIdx.x;
    int q0 = b & 3;            // split (msg) / h-block (layer)
    int mb = (b >> 2) & 15;
    int d  = b >> 6;
    int grp = d * 16 + mb;
    int t = threadIdx.x;

    // load resident weight slice: rows 0..255 of g_W[d], cols q0*128..+128
    {
        const uint32_t* __restrict__ Wsrc = g_W[d];
        for (int i = t; i < 256 * 32; i += 256) {      // uint4 granules
            int row = i >> 5, c4 = (i & 31) * 4;
            *(uint4*)&Wres[row * BS_STR + c4] =
                *(const uint4*)&Wsrc[(size_t)row * 512 + q0 * 128 + c4];
        }
    }
    __syncthreads();

    for (int s = 0; s < TT; s++) {
        msg_tile(adjs, s, q0, mb, d, Ast, Bst, &s_flag);

        layer_tile(s, 0, 0, q0, mb, d, Wres, Ast);
        __threadfence();
        __syncthreads();
        if (t == 0) {
            atomicAdd(&g_sync[80 + grp], 1u);
            while (ld_acq(&g_sync[80 + grp]) < 4u * (unsigned)(s + 1)) __nanosleep(32);
        }
        __syncthreads();

        layer_tile(s, 1, (s == TT - 1), q0, mb, d, Wres, Ast);
        if (s != TT - 1) grid_bar((unsigned)NB * (unsigned)(s + 1));
    }
}

// ============================================================
// final: y[n] = [h_f | h_b][n] . v + v[256]
// ============================================================
__global__ void k_final(float* __restrict__ out) {
    int warp = threadIdx.x >> 5;
    int lane = threadIdx.x & 31;
    int n = blockIdx.x * 8 + warp;
    float s = 0.0f;
#pragma unroll
    for (int j = lane; j < 2 * HH; j += 32) {
        float hv = (j < HH) ? g_H0f[0][(size_t)n * HH + j]
                            : g_H0f[1][(size_t)n * HH + (j - HH)];
        s += hv * g_v[j];
    }
#pragma unroll
    for (int o = 16; o > 0; o >>= 1) s += __shfl_down_sync(0xffffffffu, s, o);
    if (lane == 0) out[n] = s + g_v[2 * HH];
}

// ============================================================
extern "C" void kernel_launch(void* const* d_in, const int* in_sizes, int n_in,
                              void* d_out, int out_size) {
    const float* x     = (const float*)d_in[0];
    const float* adjs  = (const float*)d_in[1];
    const float* Winw  = (const float*)d_in[3];
    const float* Winb  = (const float*)d_in[4];
    const float* fWx   = (const float*)d_in[5];
    const float* fWh   = (const float*)d_in[6];
    const float* fWn   = (const float*)d_in[7];
    const float* fb    = (const float*)d_in[8];
    const float* bWx   = (const float*)d_in[9];
    const float* bWh   = (const float*)d_in[10];
    const float* bWn   = (const float*)d_in[11];
    const float* bb    = (const float*)d_in[12];
    const float* fc0w  = (const float*)d_in[13];
    const float* fc0b  = (const float*)d_in[14];
    const float* woutw = (const float*)d_in[15];
    const float* woutb = (const float*)d_in[16];
    float* out = (float*)d_out;

    static int smem_set = 0;
    if (!smem_set) {
        cudaFuncSetAttribute(k_steps, cudaFuncAttributeMaxDynamicSharedMemorySize,
                             SMEM_BYTES);
        smem_set = 1;
    }

    k_xs<<<dim3(2, 512), 256>>>(x, Winw, Winb);
    k_prep<<<1, 288>>>(fc0w, fc0b, woutw, woutb);
    k_wprep<<<(2 * 384 * 512 + 255) / 256, 256>>>(fWn, fWh, fWx, bWn, bWh, bWx);
    k_init<<<(2 * NN * HH) / 256, 256>>>();
    k_xb<<<dim3(4, 512, 2), 256>>>(fb, bb);

    k_steps<<<NB, 256, SMEM_BYTES>>>(adjs);

    k_final<<<NN / 8, 256>>>(out);
}

// round 12
// speedup vs baseline: 4.3223x; 1.1763x over previous
#include <cuda_runtime.h>
#include <cuda_fp16.h>
#include <math.h>
#include <stdint.h>

#define TT 32
#define NN 1024
#define FF 64
#define HH 128
#define H4 512
#define NB 128          // persistent grid size (<=148 SMs, all co-resident)

// ---- scratch (static __device__ arrays; no runtime allocation) ----
__device__ float    g_xs[TT * NN * HH];        // fp32 xs
__device__ uint32_t g_xs_h[TT * NN * (HH/2)];  // xs as half2 (pairs along h)
__device__ float    g_xbg[2][TT * NN * H4];    // xs@Wx + b, gate-gathered cols
__device__ float    g_msgp[8][NN * HH];        // split-K=4 partials per dir
__device__ uint32_t g_msg_h[2][NN * (HH/2)];   // summed msg, half2 (pairs along h)
__device__ float    g_H0f[2][NN * HH];         // final h_time fp32 (k_final)
__device__ uint32_t g_H0tf[2][NN * HH];        // h_time tf32 (msg B operand)
__device__ uint32_t g_H0h[2][NN * (HH/2)];     // h_time half2 (layer A operand)
__device__ uint32_t g_H1h[2][NN * (HH/2)];     // layer-1 h half2
__device__ float    g_C0[2][NN * HH];
__device__ float    g_C1[2][NN * HH];
__device__ uint32_t g_Wh[2][192 * 512];        // gathered fp16 [Wn;Wh;Wx], k-pair packed
__device__ float    g_v[2 * HH + 1];
// sync words (monotone per launch, reset by k_init):
//  [0] global barrier; [16+g] split-K done; [48+g] msg reduced; [80+g] layer0 done
__device__ unsigned g_sync[128];

__device__ __forceinline__ float sigm(float x) { return 1.0f / (1.0f + expf(-x)); }

__device__ __forceinline__ uint32_t f2tf(float f) {
    uint32_t u;
    asm("cvt.rna.tf32.f32 %0, %1;" : "=r"(u) : "f"(f));
    return u;
}
__device__ __forceinline__ uint32_t f2h2(float lo, float hi) {
    __half2 h = __floats2half2_rn(lo, hi);
    return *reinterpret_cast<uint32_t*>(&h);
}

// tf32 m16n8k8 (msg phase)
__device__ __forceinline__ void mma8(float* c, uint32_t a0, uint32_t a1, uint32_t a2,
                                     uint32_t a3, uint32_t b0, uint32_t b1) {
    asm volatile(
        "mma.sync.aligned.m16n8k8.row.col.f32.tf32.tf32.f32 "
        "{%0,%1,%2,%3},{%4,%5,%6,%7},{%8,%9},{%0,%1,%2,%3};"
        : "+f"(c[0]), "+f"(c[1]), "+f"(c[2]), "+f"(c[3])
        : "r"(a0), "r"(a1), "r"(a2), "r"(a3), "r"(b0), "r"(b1));
}
// fp16 m16n8k16 (layer / xb phases), fp32 accumulate
__device__ __forceinline__ void mma16(float* c, uint32_t a0, uint32_t a1, uint32_t a2,
                                      uint32_t a3, uint32_t b0, uint32_t b1) {
    asm volatile(
        "mma.sync.aligned.m16n8k16.row.col.f32.f16.f16.f32 "
        "{%0,%1,%2,%3},{%4,%5,%6,%7},{%8,%9},{%0,%1,%2,%3};"
        : "+f"(c[0]), "+f"(c[1]), "+f"(c[2]), "+f"(c[3])
        : "r"(a0), "r"(a1), "r"(a2), "r"(a3), "r"(b0), "r"(b1));
}

__device__ __forceinline__ void cpa16(uint32_t dst, const void* src) {
    asm volatile("cp.async.cg.shared.global [%0], [%1], 16;" :: "r"(dst), "l"(src));
}
__device__ __forceinline__ void cp_commit() { asm volatile("cp.async.commit_group;"); }
__device__ __forceinline__ void cp_wait1()  { asm volatile("cp.async.wait_group 1;" ::: "memory"); }
__device__ __forceinline__ uint32_t s2u(const void* p) {
    return (uint32_t)__cvta_generic_to_shared(p);
}
__device__ __forceinline__ unsigned ld_acq(const unsigned* p) {
    unsigned v;
    asm volatile("ld.acquire.gpu.global.u32 %0, [%1];" : "=r"(v) : "l"(p));
    return v;
}

__device__ __forceinline__ void grid_bar(unsigned target) {
    __threadfence();
    __syncthreads();
    if (threadIdx.x == 0) {
        atomicAdd(&g_sync[0], 1u);
        while (ld_acq(&g_sync[0]) < target) __nanosleep(32);
    }
    __syncthreads();
}

// smem strides (u32 units):
//  tf32 A: stride 20 (frag reads conflict-free)
//  tf32/f16 B: stride 136
//  f16 A (half2): stride 12 -> (12g+t4) mod 32 distinct over g<8,t4<4
#define AS_STR 20
#define BS_STR 136
#define A2_STR 12
#define AS_SZ (64 * AS_STR)      // 1280 (tf32 msg A stage)
#define BS_SZ (16 * BS_STR)      // 2176 (tf32 msg B stage)
#define A2_SZ (64 * A2_STR)      // 768  (f16 layer/xb A stage)
// dynamic smem layout of k_steps (u32 units):
#define W_OFF  0                 // 128 kp * 136 = 17408 : resident fp16 weights
#define A_OFF  17408             // 3 * AS_SZ = 3840 (layer reuses prefix as 3*A2_SZ)
#define MB_OFF 21248             // 3 * BS_SZ = 6528
#define SMEM_U32 27776
#define SMEM_BYTES (SMEM_U32 * 4)

// ============================================================
// k_xs (fp32, once): xs = x @ Win^T + b ; fp32 + half2 copies
// ============================================================
__global__ void k_xs(const float* __restrict__ x,
                     const float* __restrict__ Ww,
                     const float* __restrict__ Wb) {
    __shared__ float As[16][68];
    __shared__ float Bs[16][64];
    int tid = threadIdx.x;
    int tx = tid & 15, ty = tid >> 4;
    int m0 = blockIdx.y * 64;
    int n0 = blockIdx.x * 64;
    float acc[4][4] = {};
    int arow = tid >> 2;
    int akq  = (tid & 3) * 4;
    int bn   = tid & 63;
    int bkq  = (tid >> 6) * 4;
    for (int k0 = 0; k0 < FF; k0 += 16) {
        float4 av = *(const float4*)&x[(size_t)(m0 + arow) * FF + k0 + akq];
        As[akq + 0][arow] = av.x; As[akq + 1][arow] = av.y;
        As[akq + 2][arow] = av.z; As[akq + 3][arow] = av.w;
        float4 bv = *(const float4*)&Ww[(size_t)(n0 + bn) * FF + k0 + bkq];
        Bs[bkq + 0][bn] = bv.x; Bs[bkq + 1][bn] = bv.y;
        Bs[bkq + 2][bn] = bv.z; Bs[bkq + 3][bn] = bv.w;
        __syncthreads();
#pragma unroll
        for (int kk = 0; kk < 16; kk++) {
            float4 b4 = *(const float4*)&Bs[kk][tx * 4];
            float a0 = As[kk][ty * 4 + 0], a1 = As[kk][ty * 4 + 1];
            float a2 = As[kk][ty * 4 + 2], a3 = As[kk][ty * 4 + 3];
            acc[0][0] += a0 * b4.x; acc[0][1] += a0 * b4.y; acc[0][2] += a0 * b4.z; acc[0][3] += a0 * b4.w;
            acc[1][0] += a1 * b4.x; acc[1][1] += a1 * b4.y; acc[1][2] += a1 * b4.z; acc[1][3] += a1 * b4.w;
            acc[2][0] += a2 * b4.x; acc[2][1] += a2 * b4.y; acc[2][2] += a2 * b4.z; acc[2][3] += a2 * b4.w;
            acc[3][0] += a3 * b4.x; acc[3][1] += a3 * b4.y; acc[3][2] += a3 * b4.z; acc[3][3] += a3 * b4.w;
        }
        __syncthreads();
    }
#pragma unroll
    for (int r = 0; r < 4; r++) {
        int m = m0 + ty * 4 + r;
        float vv[4];
#pragma unroll
        for (int c = 0; c < 4; c++) {
            int n = n0 + tx * 4 + c;
            vv[c] = acc[r][c] + Wb[n];
            g_xs[(size_t)m * HH + n] = vv[c];
        }
        int h0 = (n0 + tx * 4) >> 1;
        g_xs_h[(size_t)m * (HH/2) + h0 + 0] = f2h2(vv[0], vv[1]);
        g_xs_h[(size_t)m * (HH/2) + h0 + 1] = f2h2(vv[2], vv[3]);
    }
}

// ============================================================
// k_wprep (once): gathered fp16 weight cat [Wn;Wh;Wx], k-pair packed.
// g_Wh[d][kp*512 + c] = half2{ Wcat[2kp][gath(c)], Wcat[2kp+1][gath(c)] }
// ============================================================
__global__ void k_wprep(const float* __restrict__ fWn, const float* __restrict__ fWh,
                        const float* __restrict__ fWx,
                        const float* __restrict__ bWn, const float* __restrict__ bWh,
                        const float* __restrict__ bWx) {
    int i = blockIdx.x * blockDim.x + threadIdx.x;
    if (i >= 2 * 192 * 512) return;
    int d = i / (192 * 512);
    int rem = i - d * (192 * 512);
    int kp = rem >> 9;
    int c = rem & 511;
    int b = c >> 7, cl = c & 127, nt = cl >> 3, wi = cl & 7;
    int g = nt & 3, j = ((nt >> 2) << 3) + wi;
    int srccol = g * HH + b * 32 + j;
    int k0 = 2 * kp;
    const float* W; int kr;
    if (k0 < 128)      { W = d ? bWn : fWn; kr = k0; }
    else if (k0 < 256) { W = d ? bWh : fWh; kr = k0 - 128; }
    else               { W = d ? bWx : fWx; kr = k0 - 256; }
    float lo = W[(size_t)kr * H4 + srccol];
    float hi = W[(size_t)(kr + 1) * H4 + srccol];
    g_Wh[d][rem] = f2h2(lo, hi);
}

// ============================================================
// k_xb (fp16 TC, once): xbg[d][m][c_gathered] = xs[m,:] @ Wx_g + b_g
// C = 32768 x 512 per dir. K=128. grid (4, 512, 2). B = g_Wh kp 128..191.
// ============================================================
__global__ void __launch_bounds__(256)
k_xb(const float* __restrict__ fb, const float* __restrict__ bb) {
    __shared__ uint32_t As2[3][A2_SZ];
    __shared__ uint32_t Bs2[3][8 * BS_STR];
    int bx = blockIdx.x, by = blockIdx.y, d = blockIdx.z;
    const uint32_t* __restrict__ A = g_xs_h;
    const uint32_t* __restrict__ B = g_Wh[d] + 128 * 512;
    const float* __restrict__ bias = d ? bb : fb;

    int t = threadIdx.x, w = t >> 5, lane = t & 31, gid = lane >> 2, t4 = lane & 3;
    int wm = (w >> 1) * 16, wn = (w & 1) * 64;
    int m0 = by * 64;
    float acc[8][4] = {};
    const int NIT = 8;   // K=128 halves -> 8 k16 tiles

    auto issue = [&](int it) {
        int st = it % 3;
        if (t < 128) {
            int row = t >> 1, part = t & 1;
            cpa16(s2u(&As2[st][row * A2_STR + part * 4]),
                  &A[(size_t)(m0 + row) * (HH/2) + it * 8 + part * 4]);
        }
        int kp = t >> 5, c4 = (t & 31) * 4;
        cpa16(s2u(&Bs2[st][kp * BS_STR + c4]),
              &B[(size_t)(it * 8 + kp) * 512 + bx * 128 + c4]);
    };
    issue(0); cp_commit();
    issue(1); cp_commit();

    for (int it = 0; it < NIT; it++) {
        cp_wait1();
        __syncthreads();
        if (it + 2 < NIT) issue(it + 2);
        cp_commit();
        int st = it % 3;
        uint32_t a0 = As2[st][(wm + gid) * A2_STR + t4];
        uint32_t a1 = As2[st][(wm + gid + 8) * A2_STR + t4];
        uint32_t a2 = As2[st][(wm + gid) * A2_STR + t4 + 4];
        uint32_t a3 = As2[st][(wm + gid + 8) * A2_STR + t4 + 4];
#pragma unroll
        for (int nt = 0; nt < 8; nt++) {
            uint32_t b0 = Bs2[st][t4 * BS_STR + wn + nt * 8 + gid];
            uint32_t b1 = Bs2[st][(t4 + 4) * BS_STR + wn + nt * 8 + gid];
            mma16(acc[nt], a0, a1, a2, a3, b0, b1);
        }
        __syncthreads();
    }

    float* __restrict__ out = g_xbg[d];
#pragma unroll
    for (int nt = 0; nt < 8; nt++)
#pragma unroll
        for (int r = 0; r < 2; r++)
#pragma unroll
            for (int e = 0; e < 2; e++) {
                int m = m0 + wm + gid + r * 8;
                int c = bx * 128 + wn + nt * 8 + t4 * 2 + e;
                int b_ = c >> 7, cl = c & 127, nt2 = cl >> 3, wi = cl & 7;
                int g = nt2 & 3, j = ((nt2 >> 2) << 3) + wi;
                int src = g * HH + b_ * 32 + j;
                out[(size_t)m * H4 + c] = acc[nt][r * 2 + e] + bias[src];
            }
}

// ============================================================
// k_init: H0 = C0 = first frame (tf32 + half2); reset sync words
// ============================================================
__global__ void k_init() {
    int i = blockIdx.x * blockDim.x + threadIdx.x;
    if (i < 128) g_sync[i] = 0u;
    int d = i / (NN * HH);
    int r = i - d * (NN * HH);
    int t0 = d ? (TT - 1) : 0;
    float v = g_xs[(size_t)t0 * NN * HH + r];
    g_H0tf[d][r] = f2tf(v);
    g_C0[d][r] = v;
    if (!(r & 1)) {
        float v1 = g_xs[(size_t)t0 * NN * HH + r + 1];
        g_H0h[d][r >> 1] = f2h2(v, v1);
    }
}

// ============================================================
// k_prep: v[j] = wout_w . fc0_w[:,j] ;  v[256] = fused scalar bias
// ============================================================
__global__ void k_prep(const float* __restrict__ fc0w,
                       const float* __restrict__ fc0b,
                       const float* __restrict__ woutw,
                       const float* __restrict__ woutb) {
    int j = threadIdx.x;
    if (j < 2 * HH) {
        float s = 0.0f;
        for (int k = 0; k < HH; k++) s += woutw[k] * fc0w[(size_t)k * (2 * HH) + j];
        g_v[j] = s;
    } else if (j == 2 * HH) {
        float s = woutb[0];
        for (int k = 0; k < HH; k++) s += woutw[k] * fc0b[k];
        g_v[2 * HH] = s;
    }
}

// ============================================================
// msg tile (tf32): split sp of adj_t @ H0tf -> g_msgp; last block of
// group (d,mb) reduces 4 partials -> g_msg_h (half2); group sync.
// ============================================================
__device__ __forceinline__ void msg_tile(const float* __restrict__ adjs, int s,
                                         int sp, int mb, int d,
                                         uint32_t* Ast, uint32_t* Bst, int* s_flag) {
    int tt = d ? (TT - 1 - s) : s;
    const float* __restrict__ A = adjs + (size_t)tt * NN * NN;
    const uint32_t* __restrict__ B = g_H0tf[d];
    int grp = d * 16 + mb;

    int t = threadIdx.x, w = t >> 5, lane = t & 31, gid = lane >> 2, t4 = lane & 3;
    int wm = (w >> 1) * 16, wn = (w & 1) * 64;
    int m0 = mb * 64;
    int kbeg = sp * 256;
    float acc[8][4] = {};
    int arow = t >> 2, apart = (t & 3) * 4;
    const int NIT = 16;

    auto issue = [&](int it) {
        int st = it % 3;
        int k0 = kbeg + it * 16;
        cpa16(s2u(&Ast[st * AS_SZ + arow * AS_STR + apart]),
              &A[(size_t)(m0 + arow) * NN + k0 + apart]);
#pragma unroll
        for (int j2 = 0; j2 < 2; j2++) {
            int idx = t + 256 * j2;
            int br = idx >> 5, pc = (idx & 31) * 4;
            cpa16(s2u(&Bst[st * BS_SZ + br * BS_STR + pc]),
                  &B[(size_t)(k0 + br) * HH + pc]);
        }
    };
    issue(0); cp_commit();
    issue(1); cp_commit();

    for (int it = 0; it < NIT; it++) {
        cp_wait1();
        __syncthreads();
        if (it + 2 < NIT) issue(it + 2);
        cp_commit();
        int st = it % 3;
#pragma unroll
        for (int kk = 0; kk < 16; kk += 8) {
            uint32_t a0 = f2tf(__uint_as_float(Ast[st * AS_SZ + (wm + gid) * AS_STR + kk + t4]));
            uint32_t a1 = f2tf(__uint_as_float(Ast[st * AS_SZ + (wm + gid + 8) * AS_STR + kk + t4]));
            uint32_t a2 = f2tf(__uint_as_float(Ast[st * AS_SZ + (wm + gid) * AS_STR + kk + t4 + 4]));
            uint32_t a3 = f2tf(__uint_as_float(Ast[st * AS_SZ + (wm + gid + 8) * AS_STR + kk + t4 + 4]));
#pragma unroll
            for (int nt = 0; nt < 8; nt++) {
                uint32_t b0 = Bst[st * BS_SZ + (kk + t4) * BS_STR + wn + nt * 8 + gid];
                uint32_t b1 = Bst[st * BS_SZ + (kk + t4 + 4) * BS_STR + wn + nt * 8 + gid];
                mma8(acc[nt], a0, a1, a2, a3, b0, b1);
            }
        }
    }
    __syncthreads();

    float* __restrict__ P = g_msgp[d * 4 + sp];
#pragma unroll
    for (int nt = 0; nt < 8; nt++)
#pragma unroll
        for (int r = 0; r < 2; r++)
#pragma unroll
            for (int e = 0; e < 2; e++) {
                int m = m0 + wm + gid + r * 8;
                int c = wn + nt * 8 + t4 * 2 + e;
                P[(size_t)m * HH + c] = acc[nt][r * 2 + e];
            }
    __threadfence();
    __syncthreads();
    if (t == 0) {
        unsigned old = atomicAdd(&g_sync[16 + grp], 1u);
        *s_flag = ((old & 3u) == 3u);
    }
    __syncthreads();
    if (*s_flag) {
        __threadfence();
        const float* __restrict__ P0 = g_msgp[d * 4 + 0];
        const float* __restrict__ P1 = g_msgp[d * 4 + 1];
        const float* __restrict__ P2 = g_msgp[d * 4 + 2];
        const float* __restrict__ P3 = g_msgp[d * 4 + 3];
        uint32_t* __restrict__ O = g_msg_h[d];
        for (int i = t * 4; i < 64 * HH; i += 1024) {
            int mrow = m0 + (i >> 7);
            int hcol = i & 127;
            size_t off = (size_t)mrow * HH + hcol;
            float4 v0 = *(const float4*)&P0[off];
            float4 v1 = *(const float4*)&P1[off];
            float4 v2 = *(const float4*)&P2[off];
            float4 v3 = *(const float4*)&P3[off];
            float s0 = (v0.x + v1.x) + (v2.x + v3.x);
            float s1 = (v0.y + v1.y) + (v2.y + v3.y);
            float s2 = (v0.z + v1.z) + (v2.z + v3.z);
            float s3 = (v0.w + v1.w) + (v2.w + v3.w);
            size_t oh = (size_t)mrow * (HH/2) + (hcol >> 1);
            O[oh + 0] = f2h2(s0, s1);
            O[oh + 1] = f2h2(s2, s3);
        }
        __threadfence();
        __syncthreads();
        if (t == 0) atomicAdd(&g_sync[48 + grp], 1u);
    } else {
        if (t == 0)
            while (ld_acq(&g_sync[48 + grp]) < (unsigned)(s + 1)) __nanosleep(32);
        __syncthreads();
    }
}

// ============================================================
// layer tile (fp16 k16): z = [msg|h] @ Wres (K=256, SMEM-resident
// fp16 weights) + xbg_t + fused LSTM cell.
// ============================================================
__device__ __forceinline__ void layer_tile(int s, int layer, int writeF,
                                           int bh, int mb, int d,
                                           const uint32_t* Wres, uint32_t* Ast) {
    int tt = d ? (TT - 1 - s) : s;
    const uint32_t* __restrict__ Am = g_msg_h[d];
    const uint32_t* __restrict__ Ah = layer ? g_H1h[d] : g_H0h[d];
    const float* __restrict__ Cin  = layer ? g_C1[d] : g_C0[d];
    float* __restrict__ Cout = layer ? g_C0[d] : g_C1[d];
    uint32_t* __restrict__ HoutH = layer ? g_H0h[d] : g_H1h[d];
    uint32_t* __restrict__ HoutTf = g_H0tf[d];   // written only when layer==1
    float* __restrict__ HoutF = g_H0f[d];
    const float* __restrict__ xbg = g_xbg[d] + (size_t)tt * NN * H4;

    int t = threadIdx.x, w = t >> 5, lane = t & 31, gid = lane >> 2, t4 = lane & 3;
    int wm = (w >> 1) * 16, wn = (w & 1) * 64;
    int m0 = mb * 64;
    float acc[8][4] = {};
    const int NIT = 16;   // K=256 halves -> 16 k16 tiles

    auto issue = [&](int it) {
        int st = it % 3;
        if (t < 128) {
            const uint32_t* Abase = (it < 8) ? Am : Ah;
            int koh = (it & 7) * 8;
            int row = t >> 1, part = t & 1;
            cpa16(s2u(&Ast[st * A2_SZ + row * A2_STR + part * 4]),
                  &Abase[(size_t)(m0 + row) * (HH/2) + koh + part * 4]);
        }
    };
    issue(0); cp_commit();
    issue(1); cp_commit();

    for (int it = 0; it < NIT; it++) {
        cp_wait1();
        __syncthreads();
        if (it + 2 < NIT) issue(it + 2);
        cp_commit();
        int st = it % 3;
        uint32_t a0 = Ast[st * A2_SZ + (wm + gid) * A2_STR + t4];
        uint32_t a1 = Ast[st * A2_SZ + (wm + gid + 8) * A2_STR + t4];
        uint32_t a2 = Ast[st * A2_SZ + (wm + gid) * A2_STR + t4 + 4];
        uint32_t a3 = Ast[st * A2_SZ + (wm + gid + 8) * A2_STR + t4 + 4];
#pragma unroll
        for (int nt = 0; nt < 8; nt++) {
            uint32_t b0 = Wres[(it * 8 + t4) * BS_STR + wn + nt * 8 + gid];
            uint32_t b1 = Wres[(it * 8 + 4 + t4) * BS_STR + wn + nt * 8 + gid];
            mma16(acc[nt], a0, a1, a2, a3, b0, b1);
        }
    }
    __syncthreads();

    // fused cell epilogue; xbg holds xs@Wx+b in gathered column order
#pragma unroll
    for (int r = 0; r < 2; r++) {
        int m = m0 + wm + gid + r * 8;
#pragma unroll
        for (int jg = 0; jg < 2; jg++) {
            float h2v[2];
#pragma unroll
            for (int e = 0; e < 2; e++) {
                int cbase = bh * 128 + wn + jg * 32 + t4 * 2 + e;
                int ci = r * 2 + e;
                float zi = acc[jg * 4 + 0][ci] + xbg[(size_t)m * H4 + cbase + 0];
                float zf = acc[jg * 4 + 1][ci] + xbg[(size_t)m * H4 + cbase + 8];
                float zo = acc[jg * 4 + 2][ci] + xbg[(size_t)m * H4 + cbase + 16];
                float zg = acc[jg * 4 + 3][ci] + xbg[(size_t)m * H4 + cbase + 24];
                int h = bh * 32 + (w & 1) * 16 + jg * 8 + t4 * 2 + e;
                float c_old = Cin[(size_t)m * HH + h];
                float c2 = sigm(zf) * c_old + sigm(zi) * tanhf(zg);
                float h2 = sigm(zo) * tanhf(c2);
                Cout[(size_t)m * HH + h] = c2;
                h2v[e] = h2;
                if (writeF) HoutF[(size_t)m * HH + h] = h2;
                if (layer) HoutTf[(size_t)m * HH + h] = f2tf(h2);
            }
            int hev = bh * 32 + (w & 1) * 16 + jg * 8 + t4 * 2;
            HoutH[(size_t)m * (HH/2) + (hev >> 1)] = f2h2(h2v[0], h2v[1]);
        }
    }
}

// ============================================================
// k_steps: persistent kernel. fp16 weight slice (128 kp x 128 cols)
// resident in SMEM; A tiles streamed per phase.
// Per step: msg(tf32) -> [group sync] -> layer0(f16) -> [group sync]
//           -> layer1(f16) -> [global barrier].
// ============================================================
__global__ void __launch_bounds__(256)
k_steps(const float* __restrict__ adjs) {
    extern __shared__ uint32_t smem[];
    uint32_t* Wres = smem + W_OFF;
    uint32_t* Ast  = smem + A_OFF;
    uint32_t* Bst  = smem + MB_OFF;
    __shared__ int s_flag;

    int b = blockIdx.x;
    int q0 = b & 3;            // split (msg) / h-block (layer)
    int mb = (b >> 2) & 15;
    int d  = b >> 6;
    int grp = d * 16 + mb;
    int t = threadIdx.x;

    // resident fp16 weights: kp 0..127 of g_Wh[d], cols q0*128..+128
    {
        const uint32_t* __restrict__ Wsrc = g_Wh[d];
        for (int i = t; i < 128 * 32; i += 256) {
            int row = i >> 5, c4 = (i & 31) * 4;
            *(uint4*)&Wres[row * BS_STR + c4] =
                *(const uint4*)&Wsrc[(size_t)row * 512 + q0 * 128 + c4];
        }
    }
    __syncthreads();

    for (int s = 0; s < TT; s++) {
        msg_tile(adjs, s, q0, mb, d, Ast, Bst, &s_flag);

        layer_tile(s, 0, 0, q0, mb, d, Wres, Ast);
        __threadfence();
        __syncthreads();
        if (t == 0) {
            atomicAdd(&g_sync[80 + grp], 1u);
            while (ld_acq(&g_sync[80 + grp]) < 4u * (unsigned)(s + 1)) __nanosleep(32);
        }
        __syncthreads();

        layer_tile(s, 1, (s == TT - 1), q0, mb, d, Wres, Ast);
        if (s != TT - 1) grid_bar((unsigned)NB * (unsigned)(s + 1));
    }
}

// ============================================================
// final: y[n] = [h_f | h_b][n] . v + v[256]
// ============================================================
__global__ void k_final(float* __restrict__ out) {
    int warp = threadIdx.x >> 5;
    int lane = threadIdx.x & 31;
    int n = blockIdx.x * 8 + warp;
    float s = 0.0f;
#pragma unroll
    for (int j = lane; j < 2 * HH; j += 32) {
        float hv = (j < HH) ? g_H0f[0][(size_t)n * HH + j]
                            : g_H0f[1][(size_t)n * HH + (j - HH)];
        s += hv * g_v[j];
    }
#pragma unroll
    for (int o = 16; o > 0; o >>= 1) s += __shfl_down_sync(0xffffffffu, s, o);
    if (lane == 0) out[n] = s + g_v[2 * HH];
}

// ============================================================
extern "C" void kernel_launch(void* const* d_in, const int* in_sizes, int n_in,
                              void* d_out, int out_size) {
    const float* x     = (const float*)d_in[0];
    const float* adjs  = (const float*)d_in[1];
    const float* Winw  = (const float*)d_in[3];
    const float* Winb  = (const float*)d_in[4];
    const float* fWx   = (const float*)d_in[5];
    const float* fWh   = (const float*)d_in[6];
    const float* fWn   = (const float*)d_in[7];
    const float* fb    = (const float*)d_in[8];
    const float* bWx   = (const float*)d_in[9];
    const float* bWh   = (const float*)d_in[10];
    const float* bWn   = (const float*)d_in[11];
    const float* bb    = (const float*)d_in[12];
    const float* fc0w  = (const float*)d_in[13];
    const float* fc0b  = (const float*)d_in[14];
    const float* woutw = (const float*)d_in[15];
    const float* woutb = (const float*)d_in[16];
    float* out = (float*)d_out;

    static int smem_set = 0;
    if (!smem_set) {
        cudaFuncSetAttribute(k_steps, cudaFuncAttributeMaxDynamicSharedMemorySize,
                             SMEM_BYTES);
        smem_set = 1;
    }

    k_xs<<<dim3(2, 512), 256>>>(x, Winw, Winb);
    k_prep<<<1, 288>>>(fc0w, fc0b, woutw, woutb);
    k_wprep<<<(2 * 192 * 512 + 255) / 256, 256>>>(fWn, fWh, fWx, bWn, bWh, bWx);
    k_init<<<(2 * NN * HH) / 256, 256>>>();
    k_xb<<<dim3(4, 512, 2), 256>>>(fb, bb);

    k_steps<<<NB, 256, SMEM_BYTES>>>(adjs);

    k_final<<<NN / 8, 256>>>(out);
}

// round 15
// speedup vs baseline: 4.5054x; 1.0424x over previous
#include <cuda_runtime.h>
#include <cuda_fp16.h>
#include <math.h>
#include <stdint.h>

#define TT 32
#define NN 1024
#define FF 64
#define HH 128
#define H4 512
#define NB 128          // persistent grid size (<=148 SMs, all co-resident)

// ---- scratch (static __device__ arrays; no runtime allocation) ----
__device__ float    g_xs[TT * NN * HH];        // fp32 xs
__device__ uint32_t g_xs_h[TT * NN * (HH/2)];  // xs as half2 (pairs along h)
__device__ float    g_xbg[2][TT * NN * H4];    // xs@Wx + b, gate-gathered cols
__device__ uint32_t g_adj_h[TT * NN * (NN/2)]; // adj as half2, k-pair packed (67 MB)
__device__ float    g_msgp[8][NN * HH];        // split-K=4 partials per dir
__device__ uint32_t g_msg_h[2][NN * (HH/2)];   // summed msg, half2 (pairs along h)
__device__ float    g_H0f[2][NN * HH];         // final h_time fp32 (k_final)
__device__ uint32_t g_H0kp[2][(NN/2) * HH];    // h_time half2, k-pair packed (msg B)
__device__ uint32_t g_H0h[2][NN * (HH/2)];     // h_time half2, h-packed (layer A)
__device__ uint32_t g_H1h[2][NN * (HH/2)];     // layer-1 h half2
__device__ float    g_C0[2][NN * HH];
__device__ float    g_C1[2][NN * HH];
__device__ uint32_t g_Wh[2][192 * 512];        // gathered fp16 [Wn;Wh;Wx], k-pair packed
__device__ float    g_v[2 * HH + 1];
// sync words (monotone per launch, reset by k_init):
//  [0] global barrier; [16+g] split-K done; [48+g] msg reduced; [80+g] layer0 done
__device__ unsigned g_sync[128];

__device__ __forceinline__ float sigm(float x) { return 1.0f / (1.0f + expf(-x)); }

__device__ __forceinline__ uint32_t f2h2(float lo, float hi) {
    __half2 h = __floats2half2_rn(lo, hi);
    return *reinterpret_cast<uint32_t*>(&h);
}

// fp16 m16n8k16, fp32 accumulate
__device__ __forceinline__ void mma16(float* c, uint32_t a0, uint32_t a1, uint32_t a2,
                                      uint32_t a3, uint32_t b0, uint32_t b1) {
    asm volatile(
        "mma.sync.aligned.m16n8k16.row.col.f32.f16.f16.f32 "
        "{%0,%1,%2,%3},{%4,%5,%6,%7},{%8,%9},{%0,%1,%2,%3};"
        : "+f"(c[0]), "+f"(c[1]), "+f"(c[2]), "+f"(c[3])
        : "r"(a0), "r"(a1), "r"(a2), "r"(a3), "r"(b0), "r"(b1));
}

__device__ __forceinline__ void cpa16(uint32_t dst, const void* src) {
    asm volatile("cp.async.cg.shared.global [%0], [%1], 16;" :: "r"(dst), "l"(src));
}
__device__ __forceinline__ void cp_commit() { asm volatile("cp.async.commit_group;"); }
__device__ __forceinline__ void cp_wait1()  { asm volatile("cp.async.wait_group 1;" ::: "memory"); }
__device__ __forceinline__ uint32_t s2u(const void* p) {
    return (uint32_t)__cvta_generic_to_shared(p);
}
__device__ __forceinline__ unsigned ld_acq(const unsigned* p) {
    unsigned v;
    asm volatile("ld.acquire.gpu.global.u32 %0, [%1];" : "=r"(v) : "l"(p));
    return v;
}

__device__ __forceinline__ void grid_bar(unsigned target) {
    __threadfence();
    __syncthreads();
    if (threadIdx.x == 0) {
        atomicAdd(&g_sync[0], 1u);
        while (ld_acq(&g_sync[0]) < target) __nanosleep(32);
    }
    __syncthreads();
}

// smem strides (u32 units):
//  f16 A (half2 kp): stride 12 -> (12g+t4) mod 32 distinct
//  f16 B (kp rows):  stride 136 -> (8*t4+gid) mod 32 distinct
#define A2_STR 12
#define BS_STR 136
#define A2_SZ (64 * A2_STR)      // 768
#define B2_SZ (8 * BS_STR)       // 1088
// dynamic smem layout of k_steps (u32 units):
#define W_OFF  0                 // 128 kp * 136 = 17408 : resident fp16 weights
#define A_OFF  17408             // 3 * A2_SZ = 2304
#define B_OFF  19712             // 3 * B2_SZ = 3264
#define SMEM_U32 22976
#define SMEM_BYTES (SMEM_U32 * 4)   // 91904 B

// ============================================================
// k_xs (fp32, once): xs = x @ Win^T + b ; fp32 + half2 copies
// ============================================================
__global__ void k_xs(const float* __restrict__ x,
                     const float* __restrict__ Ww,
                     const float* __restrict__ Wb) {
    __shared__ float As[16][68];
    __shared__ float Bs[16][64];
    int tid = threadIdx.x;
    int tx = tid & 15, ty = tid >> 4;
    int m0 = blockIdx.y * 64;
    int n0 = blockIdx.x * 64;
    float acc[4][4] = {};
    int arow = tid >> 2;
    int akq  = (tid & 3) * 4;
    int bn   = tid & 63;
    int bkq  = (tid >> 6) * 4;
    for (int k0 = 0; k0 < FF; k0 += 16) {
        float4 av = *(const float4*)&x[(size_t)(m0 + arow) * FF + k0 + akq];
        As[akq + 0][arow] = av.x; As[akq + 1][arow] = av.y;
        As[akq + 2][arow] = av.z; As[akq + 3][arow] = av.w;
        float4 bv = *(const float4*)&Ww[(size_t)(n0 + bn) * FF + k0 + bkq];
        Bs[bkq + 0][bn] = bv.x; Bs[bkq + 1][bn] = bv.y;
        Bs[bkq + 2][bn] = bv.z; Bs[bkq + 3][bn] = bv.w;
        __syncthreads();
#pragma unroll
        for (int kk = 0; kk < 16; kk++) {
            float4 b4 = *(const float4*)&Bs[kk][tx * 4];
            float a0 = As[kk][ty * 4 + 0], a1 = As[kk][ty * 4 + 1];
            float a2 = As[kk][ty * 4 + 2], a3 = As[kk][ty * 4 + 3];
            acc[0][0] += a0 * b4.x; acc[0][1] += a0 * b4.y; acc[0][2] += a0 * b4.z; acc[0][3] += a0 * b4.w;
            acc[1][0] += a1 * b4.x; acc[1][1] += a1 * b4.y; acc[1][2] += a1 * b4.z; acc[1][3] += a1 * b4.w;
            acc[2][0] += a2 * b4.x; acc[2][1] += a2 * b4.y; acc[2][2] += a2 * b4.z; acc[2][3] += a2 * b4.w;
            acc[3][0] += a3 * b4.x; acc[3][1] += a3 * b4.y; acc[3][2] += a3 * b4.z; acc[3][3] += a3 * b4.w;
        }
        __syncthreads();
    }
#pragma unroll
    for (int r = 0; r < 4; r++) {
        int m = m0 + ty * 4 + r;
        float vv[4];
#pragma unroll
        for (int c = 0; c < 4; c++) {
            int n = n0 + tx * 4 + c;
            vv[c] = acc[r][c] + Wb[n];
            g_xs[(size_t)m * HH + n] = vv[c];
        }
        int h0 = (n0 + tx * 4) >> 1;
        g_xs_h[(size_t)m * (HH/2) + h0 + 0] = f2h2(vv[0], vv[1]);
        g_xs_h[(size_t)m * (HH/2) + h0 + 1] = f2h2(vv[2], vv[3]);
    }
}

// ============================================================
// k_adj (once): adjs fp32 -> fp16 half2, k-pair packed.
// ============================================================
__global__ void k_adj(const float* __restrict__ adjs) {
    size_t i = (size_t)blockIdx.x * blockDim.x + threadIdx.x;
    if (i >= (size_t)TT * NN * (NN/2)) return;
    float2 v = ((const float2*)adjs)[i];
    g_adj_h[i] = f2h2(v.x, v.y);
}

// ============================================================
// k_wprep (once): gathered fp16 weight cat [Wn;Wh;Wx], k-pair packed.
// ============================================================
__global__ void k_wprep(const float* __restrict__ fWn, const float* __restrict__ fWh,
                        const float* __restrict__ fWx,
                        const float* __restrict__ bWn, const float* __restrict__ bWh,
                        const float* __restrict__ bWx) {
    int i = blockIdx.x * blockDim.x + threadIdx.x;
    if (i >= 2 * 192 * 512) return;
    int d = i / (192 * 512);
    int rem = i - d * (192 * 512);
    int kp = rem >> 9;
    int c = rem & 511;
    int b = c >> 7, cl = c & 127, nt = cl >> 3, wi = cl & 7;
    int g = nt & 3, j = ((nt >> 2) << 3) + wi;
    int srccol = g * HH + b * 32 + j;
    int k0 = 2 * kp;
    const float* W; int kr;
    if (k0 < 128)      { W = d ? bWn : fWn; kr = k0; }
    else if (k0 < 256) { W = d ? bWh : fWh; kr = k0 - 128; }
    else               { W = d ? bWx : fWx; kr = k0 - 256; }
    float lo = W[(size_t)kr * H4 + srccol];
    float hi = W[(size_t)(kr + 1) * H4 + srccol];
    g_Wh[d][rem] = f2h2(lo, hi);
}

// ============================================================
// k_xb (fp16 TC, once): xbg[d][m][c_gathered] = xs[m,:] @ Wx_g + b_g
// ============================================================
__global__ void __launch_bounds__(256)
k_xb(const float* __restrict__ fb, const float* __restrict__ bb) {
    __shared__ uint32_t As2[3][A2_SZ];
    __shared__ uint32_t Bs2[3][B2_SZ];
    int bx = blockIdx.x, by = blockIdx.y, d = blockIdx.z;
    const uint32_t* __restrict__ A = g_xs_h;
    const uint32_t* __restrict__ B = g_Wh[d] + 128 * 512;
    const float* __restrict__ bias = d ? bb : fb;

    int t = threadIdx.x, w = t >> 5, lane = t & 31, gid = lane >> 2, t4 = lane & 3;
    int wm = (w >> 1) * 16, wn = (w & 1) * 64;
    int m0 = by * 64;
    float acc[8][4] = {};
    const int NIT = 8;

    auto issue = [&](int it) {
        int st = it % 3;
        if (t < 128) {
            int row = t >> 1, part = t & 1;
            cpa16(s2u(&As2[st][row * A2_STR + part * 4]),
                  &A[(size_t)(m0 + row) * (HH/2) + it * 8 + part * 4]);
        }
        int kp = t >> 5, c4 = (t & 31) * 4;
        cpa16(s2u(&Bs2[st][kp * BS_STR + c4]),
              &B[(size_t)(it * 8 + kp) * 512 + bx * 128 + c4]);
    };
    issue(0); cp_commit();
    issue(1); cp_commit();

    for (int it = 0; it < NIT; it++) {
        cp_wait1();
        __syncthreads();
        if (it + 2 < NIT) issue(it + 2);
        cp_commit();
        int st = it % 3;
        uint32_t a0 = As2[st][(wm + gid) * A2_STR + t4];
        uint32_t a1 = As2[st][(wm + gid + 8) * A2_STR + t4];
        uint32_t a2 = As2[st][(wm + gid) * A2_STR + t4 + 4];
        uint32_t a3 = As2[st][(wm + gid + 8) * A2_STR + t4 + 4];
#pragma unroll
        for (int nt = 0; nt < 8; nt++) {
            uint32_t b0 = Bs2[st][t4 * BS_STR + wn + nt * 8 + gid];
            uint32_t b1 = Bs2[st][(t4 + 4) * BS_STR + wn + nt * 8 + gid];
            mma16(acc[nt], a0, a1, a2, a3, b0, b1);
        }
        __syncthreads();
    }

    float* __restrict__ out = g_xbg[d];
#pragma unroll
    for (int nt = 0; nt < 8; nt++)
#pragma unroll
        for (int r = 0; r < 2; r++)
#pragma unroll
            for (int e = 0; e < 2; e++) {
                int m = m0 + wm + gid + r * 8;
                int c = bx * 128 + wn + nt * 8 + t4 * 2 + e;
                int b_ = c >> 7, cl = c & 127, nt2 = cl >> 3, wi = cl & 7;
                int g = nt2 & 3, j = ((nt2 >> 2) << 3) + wi;
                int src = g * HH + b_ * 32 + j;
                out[(size_t)m * H4 + c] = acc[nt][r * 2 + e] + bias[src];
            }
}

// ============================================================
// k_init: H0 = C0 = first frame (h-packed + kp-packed); reset sync
// ============================================================
__global__ void k_init() {
    int i = blockIdx.x * blockDim.x + threadIdx.x;
    if (i < 128) g_sync[i] = 0u;
    int d = i / (NN * HH);
    int r = i - d * (NN * HH);
    int t0 = d ? (TT - 1) : 0;
    const float* src = g_xs + (size_t)t0 * NN * HH;
    float v = src[r];
    g_C0[d][r] = v;
    int row = r >> 7, h = r & 127;
    if (!(r & 1))                 // h-packed pairs (h, h+1)
        g_H0h[d][r >> 1] = f2h2(v, src[r + 1]);
    if (!(row & 1))               // kp-packed pairs (row, row+1)
        g_H0kp[d][(size_t)(row >> 1) * HH + h] = f2h2(v, src[r + HH]);
}

// ============================================================
// k_prep: v[j] = wout_w . fc0_w[:,j] ;  v[256] = fused scalar bias
// ============================================================
__global__ void k_prep(const float* __restrict__ fc0w,
                       const float* __restrict__ fc0b,
                       const float* __restrict__ woutw,
                       const float* __restrict__ woutb) {
    int j = threadIdx.x;
    if (j < 2 * HH) {
        float s = 0.0f;
        for (int k = 0; k < HH; k++) s += woutw[k] * fc0w[(size_t)k * (2 * HH) + j];
        g_v[j] = s;
    } else if (j == 2 * HH) {
        float s = woutb[0];
        for (int k = 0; k < HH; k++) s += woutw[k] * fc0b[k];
        g_v[2 * HH] = s;
    }
}

// ============================================================
// msg tile (fp16 k16): split sp of adj_t @ H0 -> g_msgp; last block
// of group (d,mb) reduces 4 partials -> g_msg_h; group sync.
// ============================================================
__device__ __forceinline__ void msg_tile(int s, int sp, int mb, int d,
                                         uint32_t* Ast, uint32_t* Bst, int* s_flag) {
    int tt = d ? (TT - 1 - s) : s;
    const uint32_t* __restrict__ A = g_adj_h + (size_t)tt * NN * (NN/2);
    const uint32_t* __restrict__ B = g_H0kp[d];
    int grp = d * 16 + mb;

    int t = threadIdx.x, w = t >> 5, lane = t & 31, gid = lane >> 2, t4 = lane & 3;
    int wm = (w >> 1) * 16, wn = (w & 1) * 64;
    int m0 = mb * 64;
    int kpbeg = sp * 128;          // 256 K values = 128 k-pairs per split
    float acc[8][4] = {};
    const int NIT = 16;

    auto issue = [&](int it) {
        int st = it % 3;
        if (t < 128) {
            int row = t >> 1, part = t & 1;
            cpa16(s2u(&Ast[st * A2_SZ + row * A2_STR + part * 4]),
                  &A[(size_t)(m0 + row) * (NN/2) + kpbeg + it * 8 + part * 4]);
        }
        int kp = t >> 5, c4 = (t & 31) * 4;
        cpa16(s2u(&Bst[st * B2_SZ + kp * BS_STR + c4]),
              &B[(size_t)(kpbeg + it * 8 + kp) * HH + c4]);
    };
    issue(0); cp_commit();
    issue(1); cp_commit();

    for (int it = 0; it < NIT; it++) {
        cp_wait1();
        __syncthreads();
        if (it + 2 < NIT) issue(it + 2);
        cp_commit();
        int st = it % 3;
        uint32_t a0 = Ast[st * A2_SZ + (wm + gid) * A2_STR + t4];
        uint32_t a1 = Ast[st * A2_SZ + (wm + gid + 8) * A2_STR + t4];
        uint32_t a2 = Ast[st * A2_SZ + (wm + gid) * A2_STR + t4 + 4];
        uint32_t a3 = Ast[st * A2_SZ + (wm + gid + 8) * A2_STR + t4 + 4];
#pragma unroll
        for (int nt = 0; nt < 8; nt++) {
            uint32_t b0 = Bst[st * B2_SZ + t4 * BS_STR + wn + nt * 8 + gid];
            uint32_t b1 = Bst[st * B2_SZ + (t4 + 4) * BS_STR + wn + nt * 8 + gid];
            mma16(acc[nt], a0, a1, a2, a3, b0, b1);
        }
    }
    __syncthreads();

    float* __restrict__ P = g_msgp[d * 4 + sp];
#pragma unroll
    for (int nt = 0; nt < 8; nt++)
#pragma unroll
        for (int r = 0; r < 2; r++)
#pragma unroll
            for (int e = 0; e < 2; e++) {
                int m = m0 + wm + gid + r * 8;
                int c = wn + nt * 8 + t4 * 2 + e;
                P[(size_t)m * HH + c] = acc[nt][r * 2 + e];
            }
    __threadfence();
    __syncthreads();
    if (t == 0) {
        unsigned old = atomicAdd(&g_sync[16 + grp], 1u);
        *s_flag = ((old & 3u) == 3u);
    }
    __syncthreads();
    if (*s_flag) {
        __threadfence();
        const float* __restrict__ P0 = g_msgp[d * 4 + 0];
        const float* __restrict__ P1 = g_msgp[d * 4 + 1];
        const float* __restrict__ P2 = g_msgp[d * 4 + 2];
        const float* __restrict__ P3 = g_msgp[d * 4 + 3];
        uint32_t* __restrict__ O = g_msg_h[d];
        for (int i = t * 4; i < 64 * HH; i += 1024) {
            int mrow = m0 + (i >> 7);
            int hcol = i & 127;
            size_t off = (size_t)mrow * HH + hcol;
            float4 v0 = *(const float4*)&P0[off];
            float4 v1 = *(const float4*)&P1[off];
            float4 v2 = *(const float4*)&P2[off];
            float4 v3 = *(const float4*)&P3[off];
            float s0 = (v0.x + v1.x) + (v2.x + v3.x);
            float s1 = (v0.y + v1.y) + (v2.y + v3.y);
            float s2 = (v0.z + v1.z) + (v2.z + v3.z);
            float s3 = (v0.w + v1.w) + (v2.w + v3.w);
            size_t oh = (size_t)mrow * (HH/2) + (hcol >> 1);
            O[oh + 0] = f2h2(s0, s1);
            O[oh + 1] = f2h2(s2, s3);
        }
        __threadfence();
        __syncthreads();
        if (t == 0) atomicAdd(&g_sync[48 + grp], 1u);
    } else {
        if (t == 0)
            while (ld_acq(&g_sync[48 + grp]) < (unsigned)(s + 1)) __nanosleep(32);
        __syncthreads();
    }
}

// ============================================================
// layer tile (fp16 k16): z = [msg|h] @ Wres (K=256, SMEM-resident
// fp16 weights) + xbg_t + fused LSTM cell.
// layer==1 additionally emits kp-packed H0 (via shfl pair exchange).
// ============================================================
__device__ __forceinline__ void layer_tile(int s, int layer, int writeF,
                                           int bh, int mb, int d,
                                           const uint32_t* Wres, uint32_t* Ast) {
    int tt = d ? (TT - 1 - s) : s;
    const uint32_t* __restrict__ Am = g_msg_h[d];
    const uint32_t* __restrict__ Ah = layer ? g_H1h[d] : g_H0h[d];
    const float* __restrict__ Cin  = layer ? g_C1[d] : g_C0[d];
    float* __restrict__ Cout = layer ? g_C0[d] : g_C1[d];
    uint32_t* __restrict__ HoutH = layer ? g_H0h[d] : g_H1h[d];
    uint32_t* __restrict__ HoutKp = g_H0kp[d];   // written only when layer==1
    float* __restrict__ HoutF = g_H0f[d];
    const float* __restrict__ xbg = g_xbg[d] + (size_t)tt * NN * H4;

    int t = threadIdx.x, w = t >> 5, lane = t & 31, gid = lane >> 2, t4 = lane & 3;
    int wm = (w >> 1) * 16, wn = (w & 1) * 64;
    int m0 = mb * 64;
    float acc[8][4] = {};
    const int NIT = 16;   // K=256 halves -> 16 k16 tiles

    auto issue = [&](int it) {
        int st = it % 3;
        if (t < 128) {
            const uint32_t* Abase = (it < 8) ? Am : Ah;
            int koh = (it & 7) * 8;
            int row = t >> 1, part = t & 1;
            cpa16(s2u(&Ast[st * A2_SZ + row * A2_STR + part * 4]),
                  &Abase[(size_t)(m0 + row) * (HH/2) + koh + part * 4]);
        }
    };
    issue(0); cp_commit();
    issue(1); cp_commit();

    for (int it = 0; it < NIT; it++) {
        cp_wait1();
        __syncthreads();
        if (it + 2 < NIT) issue(it + 2);
        cp_commit();
        int st = it % 3;
        uint32_t a0 = Ast[st * A2_SZ + (wm + gid) * A2_STR + t4];
        uint32_t a1 = Ast[st * A2_SZ + (wm + gid + 8) * A2_STR + t4];
        uint32_t a2 = Ast[st * A2_SZ + (wm + gid) * A2_STR + t4 + 4];
        uint32_t a3 = Ast[st * A2_SZ + (wm + gid + 8) * A2_STR + t4 + 4];
#pragma unroll
        for (int nt = 0; nt < 8; nt++) {
            uint32_t b0 = Wres[(it * 8 + t4) * BS_STR + wn + nt * 8 + gid];
            uint32_t b1 = Wres[(it * 8 + 4 + t4) * BS_STR + wn + nt * 8 + gid];
            mma16(acc[nt], a0, a1, a2, a3, b0, b1);
        }
    }
    __syncthreads();

    // fused cell epilogue; xbg holds xs@Wx+b in gathered column order
#pragma unroll
    for (int r = 0; r < 2; r++) {
        int m = m0 + wm + gid + r * 8;
#pragma unroll
        for (int jg = 0; jg < 2; jg++) {
            float h2v[2];
#pragma unroll
            for (int e = 0; e < 2; e++) {
                int cbase = bh * 128 + wn + jg * 32 + t4 * 2 + e;
                int ci = r * 2 + e;
                float zi = acc[jg * 4 + 0][ci] + xbg[(size_t)m * H4 + cbase + 0];
                float zf = acc[jg * 4 + 1][ci] + xbg[(size_t)m * H4 + cbase + 8];
                float zo = acc[jg * 4 + 2][ci] + xbg[(size_t)m * H4 + cbase + 16];
                float zg = acc[jg * 4 + 3][ci] + xbg[(size_t)m * H4 + cbase + 24];
                int h = bh * 32 + (w & 1) * 16 + jg * 8 + t4 * 2 + e;
                float c_old = Cin[(size_t)m * HH + h];
                float c2 = sigm(zf) * c_old + sigm(zi) * tanhf(zg);
                float h2 = sigm(zo) * tanhf(c2);
                Cout[(size_t)m * HH + h] = c2;
                h2v[e] = h2;
                if (writeF) HoutF[(size_t)m * HH + h] = h2;
            }
            int hev = bh * 32 + (w & 1) * 16 + jg * 8 + t4 * 2;
            HoutH[(size_t)m * (HH/2) + (hev >> 1)] = f2h2(h2v[0], h2v[1]);
            // kp-packed H0 for next-step msg: partner (m^1) lives at lane^4
            float p0 = __shfl_xor_sync(0xffffffffu, h2v[0], 4);
            float p1 = __shfl_xor_sync(0xffffffffu, h2v[1], 4);
            if (layer && !(gid & 1)) {
                size_t kpoff = (size_t)(m >> 1) * HH + hev;
                HoutKp[kpoff + 0] = f2h2(h2v[0], p0);
                HoutKp[kpoff + 1] = f2h2(h2v[1], p1);
            }
        }
    }
}

// ============================================================
// k_steps: persistent kernel; fp16 weight slice resident in SMEM.
// Per step: msg(f16) -> [group sync] -> layer0(f16) -> [group sync]
//           -> layer1(f16) -> [global barrier].
// ============================================================
__global__ void __launch_bounds__(256)
k_steps() {
    extern __shared__ uint32_t smem[];
    uint32_t* Wres = smem + W_OFF;
    uint32_t* Ast  = smem + A_OFF;
    uint32_t* Bst  = smem + B_OFF;
    __shared__ int s_flag;

    int b = blockIdx.x;
    int q0 = b & 3;            // split (msg) / h-block (layer)
    int mb = (b >> 2) & 15;
    int d  = b >> 6;
    int grp = d * 16 + mb;
    int t = threadIdx.x;

    // resident fp16 weights: kp 0..127 of g_Wh[d], cols q0*128..+128
    {
        const uint32_t* __restrict__ Wsrc = g_Wh[d];
        for (int i = t; i < 128 * 32; i += 256) {
            int row = i >> 5, c4 = (i & 31) * 4;
            *(uint4*)&Wres[row * BS_STR + c4] =
                *(const uint4*)&Wsrc[(size_t)row * 512 + q0 * 128 + c4];
        }
    }
    __syncthreads();

    for (int s = 0; s < TT; s++) {
        msg_tile(s, q0, mb, d, Ast, Bst, &s_flag);

        layer_tile(s, 0, 0, q0, mb, d, Wres, Ast);
        __threadfence();
        __syncthreads();
        if (t == 0) {
            atomicAdd(&g_sync[80 + grp], 1u);
            while (ld_acq(&g_sync[80 + grp]) < 4u * (unsigned)(s + 1)) __nanosleep(32);
        }
        __syncthreads();

        layer_tile(s, 1, (s == TT - 1), q0, mb, d, Wres, Ast);
        if (s != TT - 1) grid_bar((unsigned)NB * (unsigned)(s + 1));
    }
}

// ============================================================
// final: y[n] = [h_f | h_b][n] . v + v[256]
// ============================================================
__global__ void k_final(float* __restrict__ out) {
    int warp = threadIdx.x >> 5;
    int lane = threadIdx.x & 31;
    int n = blockIdx.x * 8 + warp;
    float s = 0.0f;
#pragma unroll
    for (int j = lane; j < 2 * HH; j += 32) {
        float hv = (j < HH) ? g_H0f[0][(size_t)n * HH + j]
                            : g_H0f[1][(size_t)n * HH + (j - HH)];
        s += hv * g_v[j];
    }
#pragma unroll
    for (int o = 16; o > 0; o >>= 1) s += __shfl_down_sync(0xffffffffu, s, o);
    if (lane == 0) out[n] = s + g_v[2 * HH];
}

// ============================================================
extern "C" void kernel_launch(void* const* d_in, const int* in_sizes, int n_in,
                              void* d_out, int out_size) {
    const float* x     = (const float*)d_in[0];
    const float* adjs  = (const float*)d_in[1];
    const float* Winw  = (const float*)d_in[3];
    const float* Winb  = (const float*)d_in[4];
    const float* fWx   = (const float*)d_in[5];
    const float* fWh   = (const float*)d_in[6];
    const float* fWn   = (const float*)d_in[7];
    const float* fb    = (const float*)d_in[8];
    const float* bWx   = (const float*)d_in[9];
    const float* bWh   = (const float*)d_in[10];
    const float* bWn   = (const float*)d_in[11];
    const float* bb    = (const float*)d_in[12];
    const float* fc0w  = (const float*)d_in[13];
    const float* fc0b  = (const float*)d_in[14];
    const float* woutw = (const float*)d_in[15];
    const float* woutb = (const float*)d_in[16];
    float* out = (float*)d_out;

    static int smem_set = 0;
    if (!smem_set) {
        cudaFuncSetAttribute(k_steps, cudaFuncAttributeMaxDynamicSharedMemorySize,
                             SMEM_BYTES);
        smem_set = 1;
    }

    k_xs<<<dim3(2, 512), 256>>>(x, Winw, Winb);
    k_prep<<<1, 288>>>(fc0w, fc0b, woutw, woutb);
    k_wprep<<<(2 * 192 * 512 + 255) / 256, 256>>>(fWn, fWh, fWx, bWn, bWh, bWx);
    k_adj<<<(TT * NN * (NN/2) + 255) / 256, 256>>>(adjs);
    k_init<<<(2 * NN * HH) / 256, 256>>>();
    k_xb<<<dim3(4, 512, 2), 256>>>(fb, bb);

    k_steps<<<NB, 256, SMEM_BYTES>>>();

    k_final<<<NN / 8, 256>>>(out);
}